// round 8
// baseline (speedup 1.0000x reference)
#include <cuda_runtime.h>
#include <cuda_bf16.h>
#include <cstdint>
#include <cstddef>

// Problem constants (ResidualBlock: N=50000, K=16, DIM=256, LeakyReLU slope 0.2)
#define PN    50000
#define PK    16
#define PDIM  256
#define SLOPE 0.2f

typedef __nv_bfloat16 bf16;

// ---------------------------------------------------------------------------
// Scratch (__device__ globals; no allocations allowed)
// ---------------------------------------------------------------------------
__device__ __align__(16) float g_a0[(size_t)PN * 64];     // init MLP out [N,64]
__device__ __align__(16) float g_a1[(size_t)PN * 128];    // LFA1 out     [N,128]
__device__ __align__(16) bf16 g_xhi[(size_t)PN * 256];
__device__ __align__(16) bf16 g_xlo[(size_t)PN * 256];
__device__ __align__(16) bf16 g_a2hi[(size_t)PN * 256];
__device__ __align__(16) bf16 g_a2lo[(size_t)PN * 256];
__device__ __align__(16) bf16 g_wres_hi[256 * 256];   // transposed: [n][k]
__device__ __align__(16) bf16 g_wres_lo[256 * 256];
__device__ __align__(16) bf16 g_winit_hi[64 * 256];
__device__ __align__(16) bf16 g_winit_lo[64 * 256];
__device__ __align__(16) bf16 g_wfin_hi[256 * 256];
__device__ __align__(16) bf16 g_wfin_lo[256 * 256];

// ---------------------------------------------------------------------------
// PTX helpers (all plain-sm_103-legal: cp.async, ldmatrix, mma.sync)
// ---------------------------------------------------------------------------
__device__ __forceinline__ uint32_t smem_u32(const void* p) {
    uint32_t a;
    asm("{ .reg .u64 t; cvta.to.shared.u64 t, %1; cvt.u32.u64 %0, t; }"
        : "=r"(a) : "l"(p));
    return a;
}

#define CP16(dst, src) \
    asm volatile("cp.async.cg.shared.global [%0], [%1], 16;" \
                 :: "r"(dst), "l"(src) : "memory")
#define CP_COMMIT() asm volatile("cp.async.commit_group;" ::: "memory")
#define CP_WAIT(n)  asm volatile("cp.async.wait_group %0;" :: "n"(n) : "memory")

#define LDSM_X4(r, addr) \
    asm volatile("ldmatrix.sync.aligned.m8n8.x4.shared.b16 {%0,%1,%2,%3}, [%4];" \
                 : "=r"((r)[0]), "=r"((r)[1]), "=r"((r)[2]), "=r"((r)[3]) \
                 : "r"(addr))

#define MMA16816(d, a, b) \
    asm volatile("mma.sync.aligned.m16n8k16.row.col.f32.bf16.bf16.f32 " \
                 "{%0,%1,%2,%3},{%4,%5,%6,%7},{%8,%9},{%0,%1,%2,%3};" \
                 : "+f"((d)[0]), "+f"((d)[1]), "+f"((d)[2]), "+f"((d)[3]) \
                 : "r"((a)[0]), "r"((a)[1]), "r"((a)[2]), "r"((a)[3]), \
                   "r"((b)[0]), "r"((b)[1]))

// ---------------------------------------------------------------------------
// Prep kernels (bf16 hi/lo split)
// ---------------------------------------------------------------------------
__device__ __forceinline__ void bf16_split(float v, bf16& h, bf16& l)
{
    h = __float2bfloat16(v);
    l = __float2bfloat16(v - __bfloat162float(h));
}

__device__ __forceinline__ uint2 pack4_bf16(bf16 a, bf16 b, bf16 c, bf16 d)
{
    __nv_bfloat162 p0 = {a, b}, p1 = {c, d};
    uint2 r;
    r.x = *(uint32_t*)&p0;
    r.y = *(uint32_t*)&p1;
    return r;
}

__global__ __launch_bounds__(256) void split_x_kernel(
    const float* __restrict__ x, bf16* __restrict__ hi,
    bf16* __restrict__ lo, int n4)
{
    int i = blockIdx.x * blockDim.x + threadIdx.x;
    if (i >= n4) return;
    float4 v = ((const float4*)x)[i];
    bf16 h0, h1, h2, h3, l0, l1, l2, l3;
    bf16_split(v.x, h0, l0); bf16_split(v.y, h1, l1);
    bf16_split(v.z, h2, l2); bf16_split(v.w, h3, l3);
    ((uint2*)hi)[i] = pack4_bf16(h0, h1, h2, h3);
    ((uint2*)lo)[i] = pack4_bf16(l0, l1, l2, l3);
}

// All three weights: W[K=256, Ncols] f32 -> transposed split bf16 Wt[Ncols][256]
__global__ __launch_bounds__(256) void prep_weights(
    const float* __restrict__ w_res, const float* __restrict__ w_init,
    const float* __restrict__ w_fin,
    bf16* __restrict__ rh, bf16* __restrict__ rl,
    bf16* __restrict__ ih, bf16* __restrict__ il,
    bf16* __restrict__ fh, bf16* __restrict__ fl)
{
    int i = blockIdx.x * blockDim.x + threadIdx.x;
    bf16 h, l;
    if (i < 65536) {                                  // w_res [256,256]
        int n = i >> 8, k = i & 255;
        bf16_split(w_res[(size_t)k * 256 + n], h, l);
        rh[i] = h; rl[i] = l;
    } else if (i < 81920) {                           // w_init [256,64]
        int j = i - 65536;
        int n = j >> 8, k = j & 255;
        bf16_split(w_init[(size_t)k * 64 + n], h, l);
        ih[j] = h; il[j] = l;
    } else if (i < 147456) {                          // w_fin [256,256]
        int j = i - 81920;
        int n = j >> 8, k = j & 255;
        bf16_split(w_fin[(size_t)k * 256 + n], h, l);
        fh[j] = h; fl[j] = l;
    }
}

// ---------------------------------------------------------------------------
// Tensor-core GEMM via mma.sync (HMMA), 3-stage cp.async pipeline,
// ONE __syncthreads per k-iteration:
//   C[M,Nout] = leaky(A[M,256] @ Wt^T + bias)
// 3-pass bf16 split folded into a 12-chunk virtual-K loop, fp32 accumulators.
// CTA: BM=128 x BN x BK=64, 256 threads, warp grid 2(M) x 4(N).
// ---------------------------------------------------------------------------
template <int BN>
__global__ __launch_bounds__(256) void gemm_mma(
    const bf16* __restrict__ Ahi, const bf16* __restrict__ Alo,
    const bf16* __restrict__ Bhi, const bf16* __restrict__ Blo,
    const float* __restrict__ bias, float* __restrict__ C, int M, int Nout)
{
    constexpr int BM = 128, BK = 64, SA = BK + 8;
    constexpr int STG = 3;
    constexpr int ABYTES = BM * SA * 2;
    constexpr int BBYTES = BN * SA * 2;
    constexpr int NT8 = BN / 32;
    constexpr int NPAIR = NT8 / 2;
    constexpr int NIT = 12;

    extern __shared__ __align__(16) char smem[];
    const uint32_t sa_u = smem_u32(smem);
    const uint32_t sb_u = sa_u + STG * ABYTES;

    const int tid  = threadIdx.x;
    const int lane = tid & 31;
    const int wid  = tid >> 5;
    const int warpM0 = (wid >> 2) * 64;
    const int warpN0 = (wid & 3) * (BN / 4);
    const int row0 = blockIdx.x * BM;
    const int col0 = blockIdx.y * BN;

    const int lr = tid >> 3;
    const int lc = (tid & 7) * 8;

    float acc[4][NT8][4];
#pragma unroll
    for (int mt = 0; mt < 4; mt++)
#pragma unroll
        for (int nt = 0; nt < NT8; nt++)
#pragma unroll
            for (int j = 0; j < 4; j++) acc[mt][nt][j] = 0.f;

    auto load_tile = [&](int it, int slot) {
        const int pass = it >> 2, kc = it & 3;
        const bf16* Ap = (pass == 2) ? Alo : Ahi;
        const bf16* Bp = (pass == 1) ? Blo : Bhi;
        const int kbase = kc * BK;
#pragma unroll
        for (int i = 0; i < 4; i++) {
            int r = lr + 32 * i;
            int gr = row0 + r;
            if (gr > M - 1) gr = M - 1;
            const void* src = Ap + (size_t)gr * 256 + kbase + lc;
            CP16(sa_u + slot * ABYTES + (r * SA + lc) * 2, src);
        }
#pragma unroll
        for (int i = 0; i < BN / 32; i++) {
            int r = lr + 32 * i;
            const void* src = Bp + (size_t)(col0 + r) * 256 + kbase + lc;
            CP16(sb_u + slot * BBYTES + (r * SA + lc) * 2, src);
        }
        CP_COMMIT();
    };

    load_tile(0, 0);
    load_tile(1, 1);

    for (int it = 0; it < NIT; it++) {
        CP_WAIT(STG - 2);          // tile `it` resident
        __syncthreads();           // visible to all; slot (it-1)%STG retired
        if (it + STG - 1 < NIT)
            load_tile(it + STG - 1, (it + STG - 1) % STG);

        const int slot = it % STG;
        const uint32_t aBase = sa_u + slot * ABYTES
            + ((warpM0 + (lane & 15)) * SA + (lane >> 4) * 8) * 2;
        const uint32_t bBase = sb_u + slot * BBYTES
            + ((warpN0 + ((lane >> 4) * 8) + (lane & 7)) * SA
               + ((lane >> 3) & 1) * 8) * 2;

#pragma unroll
        for (int ks = 0; ks < 4; ks++) {
            uint32_t a[4][4];
#pragma unroll
            for (int mt = 0; mt < 4; mt++)
                LDSM_X4(a[mt], aBase + mt * (16 * SA * 2) + ks * 32);

            uint32_t b[NT8][2];
#pragma unroll
            for (int np = 0; np < NPAIR; np++) {
                uint32_t t[4];
                LDSM_X4(t, bBase + np * (16 * SA * 2) + ks * 32);
                b[2 * np][0] = t[0]; b[2 * np][1] = t[1];
                b[2 * np + 1][0] = t[2]; b[2 * np + 1][1] = t[3];
            }

#pragma unroll
            for (int mt = 0; mt < 4; mt++)
#pragma unroll
                for (int nt = 0; nt < NT8; nt++)
                    MMA16816(acc[mt][nt], a[mt], b[nt]);
        }
    }

    const int erow = (lane >> 2);
    const int ecol = (lane & 3) * 2;
#pragma unroll
    for (int mt = 0; mt < 4; mt++) {
#pragma unroll
        for (int nt = 0; nt < NT8; nt++) {
            const int col = col0 + warpN0 + nt * 8 + ecol;
            const float2 b2 = *(const float2*)(bias + col);
#pragma unroll
            for (int h = 0; h < 2; h++) {
                const int row = row0 + warpM0 + mt * 16 + erow + h * 8;
                if (row >= M) continue;
                float vx = acc[mt][nt][2 * h]     + b2.x;
                float vy = acc[mt][nt][2 * h + 1] + b2.y;
                vx = vx >= 0.f ? vx : SLOPE * vx;
                vy = vy >= 0.f ? vy : SLOPE * vy;
                *(float2*)(C + (size_t)row * Nout + col) = make_float2(vx, vy);
            }
        }
    }
}

// ---------------------------------------------------------------------------
// Fused final GEMM: out = leaky(x@Wres+b_res) + leaky(a2@Wfin+b_fin)
// Two sequential accumulation phases sharing the 3-stage smem pipeline.
// ---------------------------------------------------------------------------
__global__ __launch_bounds__(256) void gemm_fused_final(
    const bf16* __restrict__ xhi, const bf16* __restrict__ xlo,
    const bf16* __restrict__ wrh, const bf16* __restrict__ wrl,
    const float* __restrict__ b_res,
    const bf16* __restrict__ a2hi, const bf16* __restrict__ a2lo,
    const bf16* __restrict__ wfh, const bf16* __restrict__ wfl,
    const float* __restrict__ b_fin,
    float* __restrict__ C, int M)
{
    constexpr int BM = 128, BN = 128, BK = 64, SA = BK + 8;
    constexpr int STG = 3;
    constexpr int ABYTES = BM * SA * 2;
    constexpr int BBYTES = BN * SA * 2;
    constexpr int NT8 = 4, NPAIR = 2, NIT = 12;

    extern __shared__ __align__(16) char smem[];
    const uint32_t sa_u = smem_u32(smem);
    const uint32_t sb_u = sa_u + STG * ABYTES;

    const int tid  = threadIdx.x;
    const int lane = tid & 31;
    const int wid  = tid >> 5;
    const int warpM0 = (wid >> 2) * 64;
    const int warpN0 = (wid & 3) * 32;
    const int row0 = blockIdx.x * BM;
    const int col0 = blockIdx.y * BN;

    const int lr = tid >> 3;
    const int lc = (tid & 7) * 8;

    float accR[4][NT8][4], accF[4][NT8][4];
#pragma unroll
    for (int mt = 0; mt < 4; mt++)
#pragma unroll
        for (int nt = 0; nt < NT8; nt++)
#pragma unroll
            for (int j = 0; j < 4; j++) { accR[mt][nt][j] = 0.f; accF[mt][nt][j] = 0.f; }

    auto run_phase = [&](float (&acc)[4][NT8][4],
                         const bf16* AH, const bf16* AL,
                         const bf16* BH, const bf16* BL) {
        auto load_tile = [&](int it, int slot) {
            const int pass = it >> 2, kc = it & 3;
            const bf16* Ap = (pass == 2) ? AL : AH;
            const bf16* Bp = (pass == 1) ? BL : BH;
            const int kbase = kc * BK;
#pragma unroll
            for (int i = 0; i < 4; i++) {
                int r = lr + 32 * i;
                int gr = row0 + r;
                if (gr > M - 1) gr = M - 1;
                const void* src = Ap + (size_t)gr * 256 + kbase + lc;
                CP16(sa_u + slot * ABYTES + (r * SA + lc) * 2, src);
            }
#pragma unroll
            for (int i = 0; i < 4; i++) {
                int r = lr + 32 * i;
                const void* src = Bp + (size_t)(col0 + r) * 256 + kbase + lc;
                CP16(sb_u + slot * BBYTES + (r * SA + lc) * 2, src);
            }
            CP_COMMIT();
        };

        __syncthreads();           // previous phase fully retired its slots
        load_tile(0, 0);
        load_tile(1, 1);

        for (int it = 0; it < NIT; it++) {
            CP_WAIT(STG - 2);
            __syncthreads();
            if (it + STG - 1 < NIT)
                load_tile(it + STG - 1, (it + STG - 1) % STG);

            const int slot = it % STG;
            const uint32_t aBase = sa_u + slot * ABYTES
                + ((warpM0 + (lane & 15)) * SA + (lane >> 4) * 8) * 2;
            const uint32_t bBase = sb_u + slot * BBYTES
                + ((warpN0 + ((lane >> 4) * 8) + (lane & 7)) * SA
                   + ((lane >> 3) & 1) * 8) * 2;

#pragma unroll
            for (int ks = 0; ks < 4; ks++) {
                uint32_t a[4][4];
#pragma unroll
                for (int mt = 0; mt < 4; mt++)
                    LDSM_X4(a[mt], aBase + mt * (16 * SA * 2) + ks * 32);

                uint32_t b[NT8][2];
#pragma unroll
                for (int np = 0; np < NPAIR; np++) {
                    uint32_t t[4];
                    LDSM_X4(t, bBase + np * (16 * SA * 2) + ks * 32);
                    b[2 * np][0] = t[0]; b[2 * np][1] = t[1];
                    b[2 * np + 1][0] = t[2]; b[2 * np + 1][1] = t[3];
                }

#pragma unroll
                for (int mt = 0; mt < 4; mt++)
#pragma unroll
                    for (int nt = 0; nt < NT8; nt++)
                        MMA16816(acc[mt][nt], a[mt], b[nt]);
            }
        }
    };

    run_phase(accR, xhi, xlo, wrh, wrl);
    run_phase(accF, a2hi, a2lo, wfh, wfl);

    // epilogue: out = leaky(accR + b_res) + leaky(accF + b_fin)
    const int erow = (lane >> 2);
    const int ecol = (lane & 3) * 2;
#pragma unroll
    for (int mt = 0; mt < 4; mt++) {
#pragma unroll
        for (int nt = 0; nt < NT8; nt++) {
            const int col = col0 + warpN0 + nt * 8 + ecol;
            const float2 br = *(const float2*)(b_res + col);
            const float2 bfi = *(const float2*)(b_fin + col);
#pragma unroll
            for (int h = 0; h < 2; h++) {
                const int row = row0 + warpM0 + mt * 16 + erow + h * 8;
                if (row >= M) continue;
                float rx = accR[mt][nt][2 * h]     + br.x;
                float ry = accR[mt][nt][2 * h + 1] + br.y;
                rx = rx >= 0.f ? rx : SLOPE * rx;
                ry = ry >= 0.f ? ry : SLOPE * ry;
                float fx = accF[mt][nt][2 * h]     + bfi.x;
                float fy = accF[mt][nt][2 * h + 1] + bfi.y;
                fx = fx >= 0.f ? fx : SLOPE * fx;
                fy = fy >= 0.f ? fy : SLOPE * fy;
                *(float2*)(C + (size_t)row * 256 + col) =
                    make_float2(rx + fx, ry + fy);
            }
        }
    }
}

// ---------------------------------------------------------------------------
// LFA1 (D=64, f32 out [N,128]): lane owns 2 cols; one LDG.64 per gathered row.
// ---------------------------------------------------------------------------
__global__ __launch_bounds__(512) void lfa1_kernel(
    const float* __restrict__ geom, const int* __restrict__ idx,
    const float* __restrict__ feat, float* __restrict__ out,
    const float* __restrict__ wg, const float* __restrict__ bg, int N)
{
    __shared__ float sw[4][64];
    __shared__ float sb[64];
    for (int i = threadIdx.x; i < 4 * 64; i += blockDim.x) sw[i >> 6][i & 63] = wg[i];
    for (int i = threadIdx.x; i < 64; i += blockDim.x) sb[i] = bg[i];
    __syncthreads();

    const int warp = threadIdx.x >> 5;
    const int lane = threadIdx.x & 31;
    const int wpb  = blockDim.x >> 5;
    const int d0   = lane * 2;

    const float2 w0 = *(const float2*)&sw[0][d0];
    const float2 w1 = *(const float2*)&sw[1][d0];
    const float2 w2 = *(const float2*)&sw[2][d0];
    const float2 w3 = *(const float2*)&sw[3][d0];
    const float2 bb = *(const float2*)&sb[d0];
    const float inv = 1.0f / (float)PK;

    for (int n = blockIdx.x * wpb + warp; n < N; n += gridDim.x * wpb) {
        int rows[PK];
        const int4* ip = (const int4*)(idx + (size_t)n * PK);
#pragma unroll
        for (int k4 = 0; k4 < PK / 4; k4++) {
            int4 r = ip[k4];
            rows[4 * k4 + 0] = r.x; rows[4 * k4 + 1] = r.y;
            rows[4 * k4 + 2] = r.z; rows[4 * k4 + 3] = r.w;
        }

        float2 t[PK];
#pragma unroll
        for (int k = 0; k < PK; k++)
            t[k] = *(const float2*)(feat + (size_t)rows[k] * 64 + d0);

        float2 accG = {0.f, 0.f};
        const float4* gp = (const float4*)(geom + (size_t)n * (PK * 4));
#pragma unroll
        for (int k = 0; k < PK; k++) {
            const float4 g = gp[k];
            float vx = bb.x, vy = bb.y;
            vx = fmaf(g.x, w0.x, vx); vy = fmaf(g.x, w0.y, vy);
            vx = fmaf(g.y, w1.x, vx); vy = fmaf(g.y, w1.y, vy);
            vx = fmaf(g.z, w2.x, vx); vy = fmaf(g.z, w2.y, vy);
            vx = fmaf(g.w, w3.x, vx); vy = fmaf(g.w, w3.y, vy);
            vx = vx >= 0.f ? vx : SLOPE * vx;
            vy = vy >= 0.f ? vy : SLOPE * vy;
            accG.x += vx; accG.y += vy;
        }

        float2 accF = {0.f, 0.f};
#pragma unroll
        for (int k = 0; k < PK; k++) { accF.x += t[k].x; accF.y += t[k].y; }

        float* o = out + (size_t)n * 128;
        *(float2*)(o + d0)      = make_float2(accG.x * inv, accG.y * inv);
        *(float2*)(o + 64 + d0) = make_float2(accF.x * inv, accF.y * inv);
    }
}

// ---------------------------------------------------------------------------
// LFA2 (D=128): lane owns 4 cols (LDG.128 per gathered row); writes split bf16.
// ---------------------------------------------------------------------------
__global__ __launch_bounds__(512) void lfa2_split_kernel(
    const float* __restrict__ geom, const int* __restrict__ idx,
    const float* __restrict__ feat, bf16* __restrict__ ohi,
    bf16* __restrict__ olo,
    const float* __restrict__ wg, const float* __restrict__ bg, int N)
{
    __shared__ float sw[4][128];
    __shared__ float sb[128];
    for (int i = threadIdx.x; i < 4 * 128; i += blockDim.x) sw[i >> 7][i & 127] = wg[i];
    for (int i = threadIdx.x; i < 128; i += blockDim.x) sb[i] = bg[i];
    __syncthreads();

    const int warp = threadIdx.x >> 5;
    const int lane = threadIdx.x & 31;
    const int wpb  = blockDim.x >> 5;
    const int d0   = lane * 4;

    const float4 w0 = *(const float4*)&sw[0][d0];
    const float4 w1 = *(const float4*)&sw[1][d0];
    const float4 w2 = *(const float4*)&sw[2][d0];
    const float4 w3 = *(const float4*)&sw[3][d0];
    const float4 bb = *(const float4*)&sb[d0];
    const float inv = 1.0f / (float)PK;

    for (int n = blockIdx.x * wpb + warp; n < N; n += gridDim.x * wpb) {
        int rows[PK];
        const int4* ip = (const int4*)(idx + (size_t)n * PK);
#pragma unroll
        for (int k4 = 0; k4 < PK / 4; k4++) {
            int4 r = ip[k4];
            rows[4 * k4 + 0] = r.x; rows[4 * k4 + 1] = r.y;
            rows[4 * k4 + 2] = r.z; rows[4 * k4 + 3] = r.w;
        }

        float4 accF = {0.f, 0.f, 0.f, 0.f};
#pragma unroll
        for (int kb = 0; kb < PK; kb += 8) {
            float4 t[8];
#pragma unroll
            for (int j = 0; j < 8; j++)
                t[j] = *(const float4*)(feat + (size_t)rows[kb + j] * 128 + d0);
#pragma unroll
            for (int j = 0; j < 8; j++) {
                accF.x += t[j].x; accF.y += t[j].y;
                accF.z += t[j].z; accF.w += t[j].w;
            }
        }

        float4 accG = {0.f, 0.f, 0.f, 0.f};
        const float4* gp = (const float4*)(geom + (size_t)n * (PK * 4));
#pragma unroll
        for (int k = 0; k < PK; k++) {
            const float4 g = gp[k];
            float vx = bb.x, vy = bb.y, vz = bb.z, vw = bb.w;
            vx = fmaf(g.x, w0.x, vx); vy = fmaf(g.x, w0.y, vy);
            vz = fmaf(g.x, w0.z, vz); vw = fmaf(g.x, w0.w, vw);
            vx = fmaf(g.y, w1.x, vx); vy = fmaf(g.y, w1.y, vy);
            vz = fmaf(g.y, w1.z, vz); vw = fmaf(g.y, w1.w, vw);
            vx = fmaf(g.z, w2.x, vx); vy = fmaf(g.z, w2.y, vy);
            vz = fmaf(g.z, w2.z, vz); vw = fmaf(g.z, w2.w, vw);
            vx = fmaf(g.w, w3.x, vx); vy = fmaf(g.w, w3.y, vy);
            vz = fmaf(g.w, w3.z, vz); vw = fmaf(g.w, w3.w, vw);
            vx = vx >= 0.f ? vx : SLOPE * vx;
            vy = vy >= 0.f ? vy : SLOPE * vy;
            vz = vz >= 0.f ? vz : SLOPE * vz;
            vw = vw >= 0.f ? vw : SLOPE * vw;
            accG.x += vx; accG.y += vy; accG.z += vz; accG.w += vw;
        }

        const size_t base = (size_t)n * 256;
        bf16 h0, h1, h2, h3, l0, l1, l2, l3;
        bf16_split(accG.x * inv, h0, l0); bf16_split(accG.y * inv, h1, l1);
        bf16_split(accG.z * inv, h2, l2); bf16_split(accG.w * inv, h3, l3);
        *(uint2*)(ohi + base + d0) = pack4_bf16(h0, h1, h2, h3);
        *(uint2*)(olo + base + d0) = pack4_bf16(l0, l1, l2, l3);
        bf16_split(accF.x * inv, h0, l0); bf16_split(accF.y * inv, h1, l1);
        bf16_split(accF.z * inv, h2, l2); bf16_split(accF.w * inv, h3, l3);
        *(uint2*)(ohi + base + 128 + d0) = pack4_bf16(h0, h1, h2, h3);
        *(uint2*)(olo + base + 128 + d0) = pack4_bf16(l0, l1, l2, l3);
    }
}

// ---------------------------------------------------------------------------
// Launch
// ---------------------------------------------------------------------------
extern "C" void kernel_launch(void* const* d_in, const int* in_sizes, int n_in,
                              void* d_out, int out_size)
{
    const float* x      = (const float*)d_in[0];
    const float* geom   = (const float*)d_in[1];
    const int*   idx    = (const int*)  d_in[2];
    const float* w_res  = (const float*)d_in[3];
    const float* b_res  = (const float*)d_in[4];
    const float* w_init = (const float*)d_in[5];
    const float* b_init = (const float*)d_in[6];
    const float* w_g1   = (const float*)d_in[7];
    const float* b_g1   = (const float*)d_in[8];
    const float* w_g2   = (const float*)d_in[9];
    const float* b_g2   = (const float*)d_in[10];
    const float* w_fin  = (const float*)d_in[11];
    const float* b_fin  = (const float*)d_in[12];
    float* out = (float*)d_out;

    float *a0, *a1;
    bf16 *xhi, *xlo, *a2hi, *a2lo;
    bf16 *wres_hi, *wres_lo, *winit_hi, *winit_lo, *wfin_hi, *wfin_lo;
    cudaGetSymbolAddress((void**)&a0, g_a0);
    cudaGetSymbolAddress((void**)&a1, g_a1);
    cudaGetSymbolAddress((void**)&xhi, g_xhi);
    cudaGetSymbolAddress((void**)&xlo, g_xlo);
    cudaGetSymbolAddress((void**)&a2hi, g_a2hi);
    cudaGetSymbolAddress((void**)&a2lo, g_a2lo);
    cudaGetSymbolAddress((void**)&wres_hi, g_wres_hi);
    cudaGetSymbolAddress((void**)&wres_lo, g_wres_lo);
    cudaGetSymbolAddress((void**)&winit_hi, g_winit_hi);
    cudaGetSymbolAddress((void**)&winit_lo, g_winit_lo);
    cudaGetSymbolAddress((void**)&wfin_hi, g_wfin_hi);
    cudaGetSymbolAddress((void**)&wfin_lo, g_wfin_lo);

    // 3-stage smem: BN=128 -> 110592 B; BN=64 -> 82944 B
    constexpr int SMEM128 = 3 * (128 * 72 * 2) + 3 * (128 * 72 * 2);
    constexpr int SMEM64  = 3 * (128 * 72 * 2) + 3 * (64 * 72 * 2);
    cudaFuncSetAttribute(gemm_fused_final, cudaFuncAttributeMaxDynamicSharedMemorySize, SMEM128);
    cudaFuncSetAttribute(gemm_mma<64>, cudaFuncAttributeMaxDynamicSharedMemorySize, SMEM64);

    const int M = PN;
    const int mTiles = (M + 127) / 128;             // 391
    const int lfaBlocks = (M + 15) / 16;            // 3125 (16 warps/block)

    // prep: split inputs / weights into bf16 hi+lo
    const int n4 = M * PDIM / 4;
    split_x_kernel<<<(n4 + 255) / 256, 256>>>(x, xhi, xlo, n4);
    prep_weights<<<(147456 + 255) / 256, 256>>>(w_res, w_init, w_fin,
                                                wres_hi, wres_lo,
                                                winit_hi, winit_lo,
                                                wfin_hi, wfin_lo);

    // 1) a0 = leaky(x @ w_init + b)
    gemm_mma<64><<<dim3(mTiles, 1), 256, SMEM64>>>(
        xhi, xlo, winit_hi, winit_lo, b_init, a0, M, 64);
    // 2) LFA1 -> a1 [N,128]
    lfa1_kernel<<<lfaBlocks, 512>>>(geom, idx, a0, a1, w_g1, b_g1, M);
    // 3) LFA2 -> a2 split bf16 [N,256]
    lfa2_split_kernel<<<lfaBlocks, 512>>>(geom, idx, a1, a2hi, a2lo, w_g2, b_g2, M);
    // 4) out = leaky(x@w_res+b_res) + leaky(a2@w_fin+b_fin)  (un-poisons d_out)
    gemm_fused_final<<<dim3(mTiles, 2), 256, SMEM128>>>(
        xhi, xlo, wres_hi, wres_lo, b_res,
        a2hi, a2lo, wfin_hi, wfin_lo, b_fin, out, M);
}

// round 9
// speedup vs baseline: 1.1233x; 1.1233x over previous
#include <cuda_runtime.h>
#include <cuda_bf16.h>
#include <cstdint>
#include <cstddef>

// Problem constants (ResidualBlock: N=50000, K=16, DIM=256, LeakyReLU slope 0.2)
#define PN    50000
#define PK    16
#define PDIM  256
#define SLOPE 0.2f

typedef __nv_bfloat16 bf16;

// ---------------------------------------------------------------------------
// Scratch (__device__ globals; no allocations allowed)
// ---------------------------------------------------------------------------
__device__ __align__(16) float g_a0[(size_t)PN * 64];     // init MLP out [N,64]
__device__ __align__(16) float g_a1[(size_t)PN * 128];    // LFA1 out     [N,128]
__device__ __align__(16) bf16 g_xhi[(size_t)PN * 256];
__device__ __align__(16) bf16 g_xlo[(size_t)PN * 256];
__device__ __align__(16) bf16 g_a2hi[(size_t)PN * 256];
__device__ __align__(16) bf16 g_a2lo[(size_t)PN * 256];
__device__ __align__(16) bf16 g_wres_hi[256 * 256];   // transposed: [n][k]
__device__ __align__(16) bf16 g_wres_lo[256 * 256];
__device__ __align__(16) bf16 g_winit_hi[64 * 256];
__device__ __align__(16) bf16 g_winit_lo[64 * 256];
__device__ __align__(16) bf16 g_wfin_hi[256 * 256];
__device__ __align__(16) bf16 g_wfin_lo[256 * 256];

// ---------------------------------------------------------------------------
// PTX helpers (all plain-sm_103-legal: cp.async, ldmatrix, mma.sync)
// ---------------------------------------------------------------------------
__device__ __forceinline__ uint32_t smem_u32(const void* p) {
    uint32_t a;
    asm("{ .reg .u64 t; cvta.to.shared.u64 t, %1; cvt.u32.u64 %0, t; }"
        : "=r"(a) : "l"(p));
    return a;
}

#define CP16(dst, src) \
    asm volatile("cp.async.cg.shared.global [%0], [%1], 16;" \
                 :: "r"(dst), "l"(src) : "memory")
#define CP_COMMIT() asm volatile("cp.async.commit_group;" ::: "memory")
#define CP_WAIT(n)  asm volatile("cp.async.wait_group %0;" :: "n"(n) : "memory")

#define LDSM_X4(r, addr) \
    asm volatile("ldmatrix.sync.aligned.m8n8.x4.shared.b16 {%0,%1,%2,%3}, [%4];" \
                 : "=r"((r)[0]), "=r"((r)[1]), "=r"((r)[2]), "=r"((r)[3]) \
                 : "r"(addr))

#define MMA16816(d, a, b) \
    asm volatile("mma.sync.aligned.m16n8k16.row.col.f32.bf16.bf16.f32 " \
                 "{%0,%1,%2,%3},{%4,%5,%6,%7},{%8,%9},{%0,%1,%2,%3};" \
                 : "+f"((d)[0]), "+f"((d)[1]), "+f"((d)[2]), "+f"((d)[3]) \
                 : "r"((a)[0]), "r"((a)[1]), "r"((a)[2]), "r"((a)[3]), \
                   "r"((b)[0]), "r"((b)[1]))

// ---------------------------------------------------------------------------
// Prep kernels (bf16 hi/lo split)
// ---------------------------------------------------------------------------
__device__ __forceinline__ void bf16_split(float v, bf16& h, bf16& l)
{
    h = __float2bfloat16(v);
    l = __float2bfloat16(v - __bfloat162float(h));
}

__device__ __forceinline__ uint2 pack4_bf16(bf16 a, bf16 b, bf16 c, bf16 d)
{
    __nv_bfloat162 p0 = {a, b}, p1 = {c, d};
    uint2 r;
    r.x = *(uint32_t*)&p0;
    r.y = *(uint32_t*)&p1;
    return r;
}

__global__ __launch_bounds__(256) void split_x_kernel(
    const float* __restrict__ x, bf16* __restrict__ hi,
    bf16* __restrict__ lo, int n4)
{
    int i = blockIdx.x * blockDim.x + threadIdx.x;
    if (i >= n4) return;
    float4 v = ((const float4*)x)[i];
    bf16 h0, h1, h2, h3, l0, l1, l2, l3;
    bf16_split(v.x, h0, l0); bf16_split(v.y, h1, l1);
    bf16_split(v.z, h2, l2); bf16_split(v.w, h3, l3);
    ((uint2*)hi)[i] = pack4_bf16(h0, h1, h2, h3);
    ((uint2*)lo)[i] = pack4_bf16(l0, l1, l2, l3);
}

// All three weights: W[K=256, Ncols] f32 -> transposed split bf16 Wt[Ncols][256]
__global__ __launch_bounds__(256) void prep_weights(
    const float* __restrict__ w_res, const float* __restrict__ w_init,
    const float* __restrict__ w_fin,
    bf16* __restrict__ rh, bf16* __restrict__ rl,
    bf16* __restrict__ ih, bf16* __restrict__ il,
    bf16* __restrict__ fh, bf16* __restrict__ fl)
{
    int i = blockIdx.x * blockDim.x + threadIdx.x;
    bf16 h, l;
    if (i < 65536) {                                  // w_res [256,256]
        int n = i >> 8, k = i & 255;
        bf16_split(w_res[(size_t)k * 256 + n], h, l);
        rh[i] = h; rl[i] = l;
    } else if (i < 81920) {                           // w_init [256,64]
        int j = i - 65536;
        int n = j >> 8, k = j & 255;
        bf16_split(w_init[(size_t)k * 64 + n], h, l);
        ih[j] = h; il[j] = l;
    } else if (i < 147456) {                          // w_fin [256,256]
        int j = i - 81920;
        int n = j >> 8, k = j & 255;
        bf16_split(w_fin[(size_t)k * 256 + n], h, l);
        fh[j] = h; fl[j] = l;
    }
}

// ---------------------------------------------------------------------------
// Tensor-core GEMM via mma.sync (HMMA), BM=64 for 2 CTAs/SM.
// CTA: 64 x BN x BK=64, 256 threads, warp grid 2(M) x 4(N), warp tile 32x(BN/4).
// 3-stage cp.async pipeline, one __syncthreads per k-iteration.
// 3-pass bf16 split folded into 12 virtual-K chunks, fp32 accumulators.
// ---------------------------------------------------------------------------
template <int BN>
__global__ __launch_bounds__(256, 2) void gemm_mma(
    const bf16* __restrict__ Ahi, const bf16* __restrict__ Alo,
    const bf16* __restrict__ Bhi, const bf16* __restrict__ Blo,
    const float* __restrict__ bias, float* __restrict__ C, int M, int Nout)
{
    constexpr int BM = 64, BK = 64, SA = BK + 8;
    constexpr int STG = 3;
    constexpr int ABYTES = BM * SA * 2;
    constexpr int BBYTES = BN * SA * 2;
    constexpr int NT8 = BN / 32;          // n8 tiles per warp (4 | 2)
    constexpr int NPAIR = NT8 / 2;
    constexpr int NIT = 12;

    extern __shared__ __align__(16) char smem[];
    const uint32_t sa_u = smem_u32(smem);
    const uint32_t sb_u = sa_u + STG * ABYTES;

    const int tid  = threadIdx.x;
    const int lane = tid & 31;
    const int wid  = tid >> 5;
    const int warpM0 = (wid >> 2) * 32;
    const int warpN0 = (wid & 3) * (BN / 4);
    const int row0 = blockIdx.x * BM;
    const int col0 = blockIdx.y * BN;

    const int lr = tid >> 3;              // 0..31
    const int lc = (tid & 7) * 8;

    float acc[2][NT8][4];
#pragma unroll
    for (int mt = 0; mt < 2; mt++)
#pragma unroll
        for (int nt = 0; nt < NT8; nt++)
#pragma unroll
            for (int j = 0; j < 4; j++) acc[mt][nt][j] = 0.f;

    auto load_tile = [&](int it, int slot) {
        const int pass = it >> 2, kc = it & 3;
        const bf16* Ap = (pass == 2) ? Alo : Ahi;
        const bf16* Bp = (pass == 1) ? Blo : Bhi;
        const int kbase = kc * BK;
#pragma unroll
        for (int i = 0; i < 2; i++) {     // A: 64 rows
            int r = lr + 32 * i;
            int gr = row0 + r;
            if (gr > M - 1) gr = M - 1;
            const void* src = Ap + (size_t)gr * 256 + kbase + lc;
            CP16(sa_u + slot * ABYTES + (r * SA + lc) * 2, src);
        }
#pragma unroll
        for (int i = 0; i < BN / 32; i++) {
            int r = lr + 32 * i;
            const void* src = Bp + (size_t)(col0 + r) * 256 + kbase + lc;
            CP16(sb_u + slot * BBYTES + (r * SA + lc) * 2, src);
        }
        CP_COMMIT();
    };

    load_tile(0, 0);
    load_tile(1, 1);

    for (int it = 0; it < NIT; it++) {
        CP_WAIT(STG - 2);
        __syncthreads();
        if (it + STG - 1 < NIT)
            load_tile(it + STG - 1, (it + STG - 1) % STG);

        const int slot = it % STG;
        const uint32_t aBase = sa_u + slot * ABYTES
            + ((warpM0 + (lane & 15)) * SA + (lane >> 4) * 8) * 2;
        const uint32_t bBase = sb_u + slot * BBYTES
            + ((warpN0 + ((lane >> 4) * 8) + (lane & 7)) * SA
               + ((lane >> 3) & 1) * 8) * 2;

#pragma unroll
        for (int ks = 0; ks < 4; ks++) {
            uint32_t a[2][4];
#pragma unroll
            for (int mt = 0; mt < 2; mt++)
                LDSM_X4(a[mt], aBase + mt * (16 * SA * 2) + ks * 32);

            uint32_t b[NT8][2];
#pragma unroll
            for (int np = 0; np < NPAIR; np++) {
                uint32_t t[4];
                LDSM_X4(t, bBase + np * (16 * SA * 2) + ks * 32);
                b[2 * np][0] = t[0]; b[2 * np][1] = t[1];
                b[2 * np + 1][0] = t[2]; b[2 * np + 1][1] = t[3];
            }

#pragma unroll
            for (int mt = 0; mt < 2; mt++)
#pragma unroll
                for (int nt = 0; nt < NT8; nt++)
                    MMA16816(acc[mt][nt], a[mt], b[nt]);
        }
    }

    const int erow = (lane >> 2);
    const int ecol = (lane & 3) * 2;
#pragma unroll
    for (int mt = 0; mt < 2; mt++) {
#pragma unroll
        for (int nt = 0; nt < NT8; nt++) {
            const int col = col0 + warpN0 + nt * 8 + ecol;
            const float2 b2 = *(const float2*)(bias + col);
#pragma unroll
            for (int h = 0; h < 2; h++) {
                const int row = row0 + warpM0 + mt * 16 + erow + h * 8;
                if (row >= M) continue;
                float vx = acc[mt][nt][2 * h]     + b2.x;
                float vy = acc[mt][nt][2 * h + 1] + b2.y;
                vx = vx >= 0.f ? vx : SLOPE * vx;
                vy = vy >= 0.f ? vy : SLOPE * vy;
                *(float2*)(C + (size_t)row * Nout + col) = make_float2(vx, vy);
            }
        }
    }
}

// ---------------------------------------------------------------------------
// Fused final GEMM: out = leaky(x@Wres+b_res) + leaky(a2@Wfin+b_fin)
// Same BM=64 / 2 CTA/SM geometry; two sequential accumulation phases.
// ---------------------------------------------------------------------------
__global__ __launch_bounds__(256, 2) void gemm_fused_final(
    const bf16* __restrict__ xhi, const bf16* __restrict__ xlo,
    const bf16* __restrict__ wrh, const bf16* __restrict__ wrl,
    const float* __restrict__ b_res,
    const bf16* __restrict__ a2hi, const bf16* __restrict__ a2lo,
    const bf16* __restrict__ wfh, const bf16* __restrict__ wfl,
    const float* __restrict__ b_fin,
    float* __restrict__ C, int M)
{
    constexpr int BM = 64, BN = 128, BK = 64, SA = BK + 8;
    constexpr int STG = 3;
    constexpr int ABYTES = BM * SA * 2;
    constexpr int BBYTES = BN * SA * 2;
    constexpr int NT8 = 4, NPAIR = 2, NIT = 12;

    extern __shared__ __align__(16) char smem[];
    const uint32_t sa_u = smem_u32(smem);
    const uint32_t sb_u = sa_u + STG * ABYTES;

    const int tid  = threadIdx.x;
    const int lane = tid & 31;
    const int wid  = tid >> 5;
    const int warpM0 = (wid >> 2) * 32;
    const int warpN0 = (wid & 3) * 32;
    const int row0 = blockIdx.x * BM;
    const int col0 = blockIdx.y * BN;

    const int lr = tid >> 3;
    const int lc = (tid & 7) * 8;

    float accR[2][NT8][4], accF[2][NT8][4];
#pragma unroll
    for (int mt = 0; mt < 2; mt++)
#pragma unroll
        for (int nt = 0; nt < NT8; nt++)
#pragma unroll
            for (int j = 0; j < 4; j++) { accR[mt][nt][j] = 0.f; accF[mt][nt][j] = 0.f; }

    auto run_phase = [&](float (&acc)[2][NT8][4],
                         const bf16* AH, const bf16* AL,
                         const bf16* BH, const bf16* BL) {
        auto load_tile = [&](int it, int slot) {
            const int pass = it >> 2, kc = it & 3;
            const bf16* Ap = (pass == 2) ? AL : AH;
            const bf16* Bp = (pass == 1) ? BL : BH;
            const int kbase = kc * BK;
#pragma unroll
            for (int i = 0; i < 2; i++) {
                int r = lr + 32 * i;
                int gr = row0 + r;
                if (gr > M - 1) gr = M - 1;
                const void* src = Ap + (size_t)gr * 256 + kbase + lc;
                CP16(sa_u + slot * ABYTES + (r * SA + lc) * 2, src);
            }
#pragma unroll
            for (int i = 0; i < 4; i++) {
                int r = lr + 32 * i;
                const void* src = Bp + (size_t)(col0 + r) * 256 + kbase + lc;
                CP16(sb_u + slot * BBYTES + (r * SA + lc) * 2, src);
            }
            CP_COMMIT();
        };

        __syncthreads();              // prior phase fully retired its slots
        load_tile(0, 0);
        load_tile(1, 1);

        for (int it = 0; it < NIT; it++) {
            CP_WAIT(STG - 2);
            __syncthreads();
            if (it + STG - 1 < NIT)
                load_tile(it + STG - 1, (it + STG - 1) % STG);

            const int slot = it % STG;
            const uint32_t aBase = sa_u + slot * ABYTES
                + ((warpM0 + (lane & 15)) * SA + (lane >> 4) * 8) * 2;
            const uint32_t bBase = sb_u + slot * BBYTES
                + ((warpN0 + ((lane >> 4) * 8) + (lane & 7)) * SA
                   + ((lane >> 3) & 1) * 8) * 2;

#pragma unroll
            for (int ks = 0; ks < 4; ks++) {
                uint32_t a[2][4];
#pragma unroll
                for (int mt = 0; mt < 2; mt++)
                    LDSM_X4(a[mt], aBase + mt * (16 * SA * 2) + ks * 32);

                uint32_t b[NT8][2];
#pragma unroll
                for (int np = 0; np < NPAIR; np++) {
                    uint32_t t[4];
                    LDSM_X4(t, bBase + np * (16 * SA * 2) + ks * 32);
                    b[2 * np][0] = t[0]; b[2 * np][1] = t[1];
                    b[2 * np + 1][0] = t[2]; b[2 * np + 1][1] = t[3];
                }

#pragma unroll
                for (int mt = 0; mt < 2; mt++)
#pragma unroll
                    for (int nt = 0; nt < NT8; nt++)
                        MMA16816(acc[mt][nt], a[mt], b[nt]);
            }
        }
    };

    run_phase(accR, xhi, xlo, wrh, wrl);
    run_phase(accF, a2hi, a2lo, wfh, wfl);

    // epilogue: out = leaky(accR + b_res) + leaky(accF + b_fin)
    const int erow = (lane >> 2);
    const int ecol = (lane & 3) * 2;
#pragma unroll
    for (int mt = 0; mt < 2; mt++) {
#pragma unroll
        for (int nt = 0; nt < NT8; nt++) {
            const int col = col0 + warpN0 + nt * 8 + ecol;
            const float2 br = *(const float2*)(b_res + col);
            const float2 bfi = *(const float2*)(b_fin + col);
#pragma unroll
            for (int h = 0; h < 2; h++) {
                const int row = row0 + warpM0 + mt * 16 + erow + h * 8;
                if (row >= M) continue;
                float rx = accR[mt][nt][2 * h]     + br.x;
                float ry = accR[mt][nt][2 * h + 1] + br.y;
                rx = rx >= 0.f ? rx : SLOPE * rx;
                ry = ry >= 0.f ? ry : SLOPE * ry;
                float fx = accF[mt][nt][2 * h]     + bfi.x;
                float fy = accF[mt][nt][2 * h + 1] + bfi.y;
                fx = fx >= 0.f ? fx : SLOPE * fx;
                fy = fy >= 0.f ? fy : SLOPE * fy;
                *(float2*)(C + (size_t)row * 256 + col) =
                    make_float2(rx + fx, ry + fy);
            }
        }
    }
}

// ---------------------------------------------------------------------------
// LFA1 (D=64, f32 out [N,128]): lane owns 2 cols; one LDG.64 per gathered row.
// 256-thread blocks (empirically best: R7 measured 35.1us vs 40.5us at 512).
// ---------------------------------------------------------------------------
__global__ __launch_bounds__(256) void lfa1_kernel(
    const float* __restrict__ geom, const int* __restrict__ idx,
    const float* __restrict__ feat, float* __restrict__ out,
    const float* __restrict__ wg, const float* __restrict__ bg, int N)
{
    __shared__ float sw[4][64];
    __shared__ float sb[64];
    for (int i = threadIdx.x; i < 4 * 64; i += blockDim.x) sw[i >> 6][i & 63] = wg[i];
    for (int i = threadIdx.x; i < 64; i += blockDim.x) sb[i] = bg[i];
    __syncthreads();

    const int warp = threadIdx.x >> 5;
    const int lane = threadIdx.x & 31;
    const int wpb  = blockDim.x >> 5;
    const int d0   = lane * 2;

    const float2 w0 = *(const float2*)&sw[0][d0];
    const float2 w1 = *(const float2*)&sw[1][d0];
    const float2 w2 = *(const float2*)&sw[2][d0];
    const float2 w3 = *(const float2*)&sw[3][d0];
    const float2 bb = *(const float2*)&sb[d0];
    const float inv = 1.0f / (float)PK;

    for (int n = blockIdx.x * wpb + warp; n < N; n += gridDim.x * wpb) {
        int rows[PK];
        const int4* ip = (const int4*)(idx + (size_t)n * PK);
#pragma unroll
        for (int k4 = 0; k4 < PK / 4; k4++) {
            int4 r = ip[k4];
            rows[4 * k4 + 0] = r.x; rows[4 * k4 + 1] = r.y;
            rows[4 * k4 + 2] = r.z; rows[4 * k4 + 3] = r.w;
        }

        float2 t[PK];
#pragma unroll
        for (int k = 0; k < PK; k++)
            t[k] = *(const float2*)(feat + (size_t)rows[k] * 64 + d0);

        float2 accG = {0.f, 0.f};
        const float4* gp = (const float4*)(geom + (size_t)n * (PK * 4));
#pragma unroll
        for (int k = 0; k < PK; k++) {
            const float4 g = gp[k];
            float vx = bb.x, vy = bb.y;
            vx = fmaf(g.x, w0.x, vx); vy = fmaf(g.x, w0.y, vy);
            vx = fmaf(g.y, w1.x, vx); vy = fmaf(g.y, w1.y, vy);
            vx = fmaf(g.z, w2.x, vx); vy = fmaf(g.z, w2.y, vy);
            vx = fmaf(g.w, w3.x, vx); vy = fmaf(g.w, w3.y, vy);
            vx = vx >= 0.f ? vx : SLOPE * vx;
            vy = vy >= 0.f ? vy : SLOPE * vy;
            accG.x += vx; accG.y += vy;
        }

        float2 accF = {0.f, 0.f};
#pragma unroll
        for (int k = 0; k < PK; k++) { accF.x += t[k].x; accF.y += t[k].y; }

        float* o = out + (size_t)n * 128;
        *(float2*)(o + d0)      = make_float2(accG.x * inv, accG.y * inv);
        *(float2*)(o + 64 + d0) = make_float2(accF.x * inv, accF.y * inv);
    }
}

// ---------------------------------------------------------------------------
// LFA2 (D=128): lane owns 4 cols (LDG.128 per gathered row); writes split bf16.
// ---------------------------------------------------------------------------
__global__ __launch_bounds__(256) void lfa2_split_kernel(
    const float* __restrict__ geom, const int* __restrict__ idx,
    const float* __restrict__ feat, bf16* __restrict__ ohi,
    bf16* __restrict__ olo,
    const float* __restrict__ wg, const float* __restrict__ bg, int N)
{
    __shared__ float sw[4][128];
    __shared__ float sb[128];
    for (int i = threadIdx.x; i < 4 * 128; i += blockDim.x) sw[i >> 7][i & 127] = wg[i];
    for (int i = threadIdx.x; i < 128; i += blockDim.x) sb[i] = bg[i];
    __syncthreads();

    const int warp = threadIdx.x >> 5;
    const int lane = threadIdx.x & 31;
    const int wpb  = blockDim.x >> 5;
    const int d0   = lane * 4;

    const float4 w0 = *(const float4*)&sw[0][d0];
    const float4 w1 = *(const float4*)&sw[1][d0];
    const float4 w2 = *(const float4*)&sw[2][d0];
    const float4 w3 = *(const float4*)&sw[3][d0];
    const float4 bb = *(const float4*)&sb[d0];
    const float inv = 1.0f / (float)PK;

    for (int n = blockIdx.x * wpb + warp; n < N; n += gridDim.x * wpb) {
        int rows[PK];
        const int4* ip = (const int4*)(idx + (size_t)n * PK);
#pragma unroll
        for (int k4 = 0; k4 < PK / 4; k4++) {
            int4 r = ip[k4];
            rows[4 * k4 + 0] = r.x; rows[4 * k4 + 1] = r.y;
            rows[4 * k4 + 2] = r.z; rows[4 * k4 + 3] = r.w;
        }

        float4 accF = {0.f, 0.f, 0.f, 0.f};
#pragma unroll
        for (int kb = 0; kb < PK; kb += 8) {
            float4 t[8];
#pragma unroll
            for (int j = 0; j < 8; j++)
                t[j] = *(const float4*)(feat + (size_t)rows[kb + j] * 128 + d0);
#pragma unroll
            for (int j = 0; j < 8; j++) {
                accF.x += t[j].x; accF.y += t[j].y;
                accF.z += t[j].z; accF.w += t[j].w;
            }
        }

        float4 accG = {0.f, 0.f, 0.f, 0.f};
        const float4* gp = (const float4*)(geom + (size_t)n * (PK * 4));
#pragma unroll
        for (int k = 0; k < PK; k++) {
            const float4 g = gp[k];
            float vx = bb.x, vy = bb.y, vz = bb.z, vw = bb.w;
            vx = fmaf(g.x, w0.x, vx); vy = fmaf(g.x, w0.y, vy);
            vz = fmaf(g.x, w0.z, vz); vw = fmaf(g.x, w0.w, vw);
            vx = fmaf(g.y, w1.x, vx); vy = fmaf(g.y, w1.y, vy);
            vz = fmaf(g.y, w1.z, vz); vw = fmaf(g.y, w1.w, vw);
            vx = fmaf(g.z, w2.x, vx); vy = fmaf(g.z, w2.y, vy);
            vz = fmaf(g.z, w2.z, vz); vw = fmaf(g.z, w2.w, vw);
            vx = fmaf(g.w, w3.x, vx); vy = fmaf(g.w, w3.y, vy);
            vz = fmaf(g.w, w3.z, vz); vw = fmaf(g.w, w3.w, vw);
            vx = vx >= 0.f ? vx : SLOPE * vx;
            vy = vy >= 0.f ? vy : SLOPE * vy;
            vz = vz >= 0.f ? vz : SLOPE * vz;
            vw = vw >= 0.f ? vw : SLOPE * vw;
            accG.x += vx; accG.y += vy; accG.z += vz; accG.w += vw;
        }

        const size_t base = (size_t)n * 256;
        bf16 h0, h1, h2, h3, l0, l1, l2, l3;
        bf16_split(accG.x * inv, h0, l0); bf16_split(accG.y * inv, h1, l1);
        bf16_split(accG.z * inv, h2, l2); bf16_split(accG.w * inv, h3, l3);
        *(uint2*)(ohi + base + d0) = pack4_bf16(h0, h1, h2, h3);
        *(uint2*)(olo + base + d0) = pack4_bf16(l0, l1, l2, l3);
        bf16_split(accF.x * inv, h0, l0); bf16_split(accF.y * inv, h1, l1);
        bf16_split(accF.z * inv, h2, l2); bf16_split(accF.w * inv, h3, l3);
        *(uint2*)(ohi + base + 128 + d0) = pack4_bf16(h0, h1, h2, h3);
        *(uint2*)(olo + base + 128 + d0) = pack4_bf16(l0, l1, l2, l3);
    }
}

// ---------------------------------------------------------------------------
// Launch
// ---------------------------------------------------------------------------
extern "C" void kernel_launch(void* const* d_in, const int* in_sizes, int n_in,
                              void* d_out, int out_size)
{
    const float* x      = (const float*)d_in[0];
    const float* geom   = (const float*)d_in[1];
    const int*   idx    = (const int*)  d_in[2];
    const float* w_res  = (const float*)d_in[3];
    const float* b_res  = (const float*)d_in[4];
    const float* w_init = (const float*)d_in[5];
    const float* b_init = (const float*)d_in[6];
    const float* w_g1   = (const float*)d_in[7];
    const float* b_g1   = (const float*)d_in[8];
    const float* w_g2   = (const float*)d_in[9];
    const float* b_g2   = (const float*)d_in[10];
    const float* w_fin  = (const float*)d_in[11];
    const float* b_fin  = (const float*)d_in[12];
    float* out = (float*)d_out;

    float *a0, *a1;
    bf16 *xhi, *xlo, *a2hi, *a2lo;
    bf16 *wres_hi, *wres_lo, *winit_hi, *winit_lo, *wfin_hi, *wfin_lo;
    cudaGetSymbolAddress((void**)&a0, g_a0);
    cudaGetSymbolAddress((void**)&a1, g_a1);
    cudaGetSymbolAddress((void**)&xhi, g_xhi);
    cudaGetSymbolAddress((void**)&xlo, g_xlo);
    cudaGetSymbolAddress((void**)&a2hi, g_a2hi);
    cudaGetSymbolAddress((void**)&a2lo, g_a2lo);
    cudaGetSymbolAddress((void**)&wres_hi, g_wres_hi);
    cudaGetSymbolAddress((void**)&wres_lo, g_wres_lo);
    cudaGetSymbolAddress((void**)&winit_hi, g_winit_hi);
    cudaGetSymbolAddress((void**)&winit_lo, g_winit_lo);
    cudaGetSymbolAddress((void**)&wfin_hi, g_wfin_hi);
    cudaGetSymbolAddress((void**)&wfin_lo, g_wfin_lo);

    // 3-stage smem, BM=64: BN=128 -> 64*72*2*3 + 128*72*2*3 = 82944 B
    //                      BN=64  -> 2 * 64*72*2*3 = 55296 B
    constexpr int SMEM128 = 3 * (64 * 72 * 2) + 3 * (128 * 72 * 2);
    constexpr int SMEM64  = 3 * (64 * 72 * 2) + 3 * (64 * 72 * 2);
    cudaFuncSetAttribute(gemm_fused_final, cudaFuncAttributeMaxDynamicSharedMemorySize, SMEM128);
    cudaFuncSetAttribute(gemm_mma<64>, cudaFuncAttributeMaxDynamicSharedMemorySize, SMEM64);

    const int M = PN;
    const int mTiles = (M + 63) / 64;               // 782
    const int lfaBlocks = (M + 7) / 8;              // 6250 (8 warps/block)

    // prep: split inputs / weights into bf16 hi+lo
    const int n4 = M * PDIM / 4;
    split_x_kernel<<<(n4 + 255) / 256, 256>>>(x, xhi, xlo, n4);
    prep_weights<<<(147456 + 255) / 256, 256>>>(w_res, w_init, w_fin,
                                                wres_hi, wres_lo,
                                                winit_hi, winit_lo,
                                                wfin_hi, wfin_lo);

    // 1) a0 = leaky(x @ w_init + b)
    gemm_mma<64><<<dim3(mTiles, 1), 256, SMEM64>>>(
        xhi, xlo, winit_hi, winit_lo, b_init, a0, M, 64);
    // 2) LFA1 -> a1 [N,128]
    lfa1_kernel<<<lfaBlocks, 256>>>(geom, idx, a0, a1, w_g1, b_g1, M);
    // 3) LFA2 -> a2 split bf16 [N,256]
    lfa2_split_kernel<<<lfaBlocks, 256>>>(geom, idx, a1, a2hi, a2lo, w_g2, b_g2, M);
    // 4) out = leaky(x@w_res+b_res) + leaky(a2@w_fin+b_fin)  (un-poisons d_out)
    gemm_fused_final<<<dim3(mTiles, 2), 256, SMEM128>>>(
        xhi, xlo, wres_hi, wres_lo, b_res,
        a2hi, a2lo, wfin_hi, wfin_lo, b_fin, out, M);
}

// round 12
// speedup vs baseline: 1.2161x; 1.0826x over previous
#include <cuda_runtime.h>
#include <cuda_bf16.h>
#include <cstdint>
#include <cstddef>

// Problem constants (ResidualBlock: N=50000, K=16, DIM=256, LeakyReLU slope 0.2)
#define PN    50000
#define PK    16
#define PDIM  256
#define SLOPE 0.2f

typedef __nv_bfloat16 bf16;

// ---------------------------------------------------------------------------
// Scratch (__device__ globals; no allocations allowed)
// ---------------------------------------------------------------------------
__device__ __align__(16) float g_a0[(size_t)PN * 64];     // init MLP out [N,64]
__device__ __align__(16) float g_a1[(size_t)PN * 128];    // LFA1 out     [N,128]
__device__ __align__(16) bf16 g_xhi[(size_t)PN * 256];
__device__ __align__(16) bf16 g_xlo[(size_t)PN * 256];
__device__ __align__(16) bf16 g_a2hi[(size_t)PN * 256];
__device__ __align__(16) bf16 g_a2lo[(size_t)PN * 256];
__device__ __align__(16) bf16 g_wres_hi[256 * 256];   // transposed: [n][k]
__device__ __align__(16) bf16 g_wres_lo[256 * 256];
__device__ __align__(16) bf16 g_winit_hi[64 * 256];
__device__ __align__(16) bf16 g_winit_lo[64 * 256];
__device__ __align__(16) bf16 g_wfin_hi[256 * 256];
__device__ __align__(16) bf16 g_wfin_lo[256 * 256];

// ---------------------------------------------------------------------------
// PTX helpers (all plain-sm_103-legal: cp.async, ldmatrix, mma.sync)
// ---------------------------------------------------------------------------
__device__ __forceinline__ uint32_t smem_u32(const void* p) {
    uint32_t a;
    asm("{ .reg .u64 t; cvta.to.shared.u64 t, %1; cvt.u32.u64 %0, t; }"
        : "=r"(a) : "l"(p));
    return a;
}

#define CP16(dst, src) \
    asm volatile("cp.async.cg.shared.global [%0], [%1], 16;" \
                 :: "r"(dst), "l"(src) : "memory")
#define CP_COMMIT() asm volatile("cp.async.commit_group;" ::: "memory")
#define CP_WAIT(n)  asm volatile("cp.async.wait_group %0;" :: "n"(n) : "memory")

#define LDSM_X4(r, addr) \
    asm volatile("ldmatrix.sync.aligned.m8n8.x4.shared.b16 {%0,%1,%2,%3}, [%4];" \
                 : "=r"((r)[0]), "=r"((r)[1]), "=r"((r)[2]), "=r"((r)[3]) \
                 : "r"(addr))

#define MMA16816(d, a, b) \
    asm volatile("mma.sync.aligned.m16n8k16.row.col.f32.bf16.bf16.f32 " \
                 "{%0,%1,%2,%3},{%4,%5,%6,%7},{%8,%9},{%0,%1,%2,%3};" \
                 : "+f"((d)[0]), "+f"((d)[1]), "+f"((d)[2]), "+f"((d)[3]) \
                 : "r"((a)[0]), "r"((a)[1]), "r"((a)[2]), "r"((a)[3]), \
                   "r"((b)[0]), "r"((b)[1]))

// ---------------------------------------------------------------------------
// Prep kernels (bf16 hi/lo split)
// ---------------------------------------------------------------------------
__device__ __forceinline__ void bf16_split(float v, bf16& h, bf16& l)
{
    h = __float2bfloat16(v);
    l = __float2bfloat16(v - __bfloat162float(h));
}

__device__ __forceinline__ uint2 pack4_bf16(bf16 a, bf16 b, bf16 c, bf16 d)
{
    __nv_bfloat162 p0 = {a, b}, p1 = {c, d};
    uint2 r;
    r.x = *(uint32_t*)&p0;
    r.y = *(uint32_t*)&p1;
    return r;
}

__global__ __launch_bounds__(256) void split_x_kernel(
    const float* __restrict__ x, bf16* __restrict__ hi,
    bf16* __restrict__ lo, int n4)
{
    int i = blockIdx.x * blockDim.x + threadIdx.x;
    if (i >= n4) return;
    float4 v = ((const float4*)x)[i];
    bf16 h0, h1, h2, h3, l0, l1, l2, l3;
    bf16_split(v.x, h0, l0); bf16_split(v.y, h1, l1);
    bf16_split(v.z, h2, l2); bf16_split(v.w, h3, l3);
    ((uint2*)hi)[i] = pack4_bf16(h0, h1, h2, h3);
    ((uint2*)lo)[i] = pack4_bf16(l0, l1, l2, l3);
}

// All three weights: W[K=256, Ncols] f32 -> transposed split bf16 Wt[Ncols][256]
__global__ __launch_bounds__(256) void prep_weights(
    const float* __restrict__ w_res, const float* __restrict__ w_init,
    const float* __restrict__ w_fin,
    bf16* __restrict__ rh, bf16* __restrict__ rl,
    bf16* __restrict__ ih, bf16* __restrict__ il,
    bf16* __restrict__ fh, bf16* __restrict__ fl)
{
    int i = blockIdx.x * blockDim.x + threadIdx.x;
    bf16 h, l;
    if (i < 65536) {                                  // w_res [256,256]
        int n = i >> 8, k = i & 255;
        bf16_split(w_res[(size_t)k * 256 + n], h, l);
        rh[i] = h; rl[i] = l;
    } else if (i < 81920) {                           // w_init [256,64]
        int j = i - 65536;
        int n = j >> 8, k = j & 255;
        bf16_split(w_init[(size_t)k * 64 + n], h, l);
        ih[j] = h; il[j] = l;
    } else if (i < 147456) {                          // w_fin [256,256]
        int j = i - 81920;
        int n = j >> 8, k = j & 255;
        bf16_split(w_fin[(size_t)k * 256 + n], h, l);
        fh[j] = h; fl[j] = l;
    }
}

// ---------------------------------------------------------------------------
// Quad-tile HMMA GEMM: per 64-wide k-chunk load Ah,Al,Bh,Bl ONCE, compute the
// three split products (ah*bh + ah*bl + al*bh) from one smem residency.
// 4 k-chunks, 2-stage double buffer, correct tail waits.
// CTA: BM=64 x BN, 256 threads, warp grid 2(M) x 4(N); 2 CTAs/SM.
// ---------------------------------------------------------------------------
template <int BN>
__global__ __launch_bounds__(256, 2) void gemm_mma(
    const bf16* __restrict__ Ahi, const bf16* __restrict__ Alo,
    const bf16* __restrict__ Bhi, const bf16* __restrict__ Blo,
    const float* __restrict__ bias, float* __restrict__ C, int M, int Nout)
{
    constexpr int BM = 64, BK = 64, SA = BK + 8;
    constexpr int AT = BM * SA * 2;          // one A split tile (9216 B)
    constexpr int BT = BN * SA * 2;          // one B split tile
    constexpr int STAGE = 2 * AT + 2 * BT;   // Ah | Al | Bh | Bl
    constexpr int NT8 = BN / 32;             // n8 tiles per warp (4 | 2)
    constexpr int NPAIR = NT8 / 2;
    constexpr int NCH = 4;                   // k-chunks

    extern __shared__ __align__(16) char smem[];
    const uint32_t s0 = smem_u32(smem);

    const int tid  = threadIdx.x;
    const int lane = tid & 31;
    const int wid  = tid >> 5;
    const int warpM0 = (wid >> 2) * 32;
    const int warpN0 = (wid & 3) * (BN / 4);
    const int row0 = blockIdx.x * BM;
    const int col0 = blockIdx.y * BN;

    const int lr = tid >> 3;                 // 0..31
    const int lc = (tid & 7) * 8;

    float acc[2][NT8][4];
#pragma unroll
    for (int mt = 0; mt < 2; mt++)
#pragma unroll
        for (int nt = 0; nt < NT8; nt++)
#pragma unroll
            for (int j = 0; j < 4; j++) acc[mt][nt][j] = 0.f;

    auto load_chunk = [&](int kc, int slot) {
        const int kbase = kc * BK;
        const uint32_t base = s0 + slot * STAGE;
#pragma unroll
        for (int i = 0; i < 2; i++) {        // A rows (hi + lo)
            int r = lr + 32 * i;
            int gr = row0 + r;
            if (gr > M - 1) gr = M - 1;
            const size_t g = (size_t)gr * 256 + kbase + lc;
            CP16(base + (r * SA + lc) * 2,       Ahi + g);
            CP16(base + AT + (r * SA + lc) * 2,  Alo + g);
        }
#pragma unroll
        for (int i = 0; i < BN / 32; i++) {  // B rows (hi + lo)
            int r = lr + 32 * i;
            const size_t g = (size_t)(col0 + r) * 256 + kbase + lc;
            CP16(base + 2 * AT + (r * SA + lc) * 2,      Bhi + g);
            CP16(base + 2 * AT + BT + (r * SA + lc) * 2, Blo + g);
        }
        CP_COMMIT();
    };

    load_chunk(0, 0);

    const uint32_t aOff = ((warpM0 + (lane & 15)) * SA + (lane >> 4) * 8) * 2;
    const uint32_t bOff = ((warpN0 + ((lane >> 4) * 8) + (lane & 7)) * SA
                          + ((lane >> 3) & 1) * 8) * 2;

    for (int it = 0; it < NCH; it++) {
        if (it + 1 < NCH) {
            load_chunk(it + 1, (it + 1) & 1);
            CP_WAIT(1);                      // chunk `it` resident
        } else {
            CP_WAIT(0);                      // tail: ALL groups complete
        }
        __syncthreads();

        const uint32_t base  = s0 + (it & 1) * STAGE;
        const uint32_t aHi = base + aOff;
        const uint32_t aLo = base + AT + aOff;
        const uint32_t bHi = base + 2 * AT + bOff;
        const uint32_t bLo = base + 2 * AT + BT + bOff;

#pragma unroll
        for (int ks = 0; ks < 4; ks++) {
            uint32_t ah[2][4], al[2][4];
#pragma unroll
            for (int mt = 0; mt < 2; mt++) {
                LDSM_X4(ah[mt], aHi + mt * (16 * SA * 2) + ks * 32);
                LDSM_X4(al[mt], aLo + mt * (16 * SA * 2) + ks * 32);
            }
            uint32_t bh[NT8][2], bl[NT8][2];
#pragma unroll
            for (int np = 0; np < NPAIR; np++) {
                uint32_t t[4];
                LDSM_X4(t, bHi + np * (16 * SA * 2) + ks * 32);
                bh[2 * np][0] = t[0]; bh[2 * np][1] = t[1];
                bh[2 * np + 1][0] = t[2]; bh[2 * np + 1][1] = t[3];
                LDSM_X4(t, bLo + np * (16 * SA * 2) + ks * 32);
                bl[2 * np][0] = t[0]; bl[2 * np][1] = t[1];
                bl[2 * np + 1][0] = t[2]; bl[2 * np + 1][1] = t[3];
            }
#pragma unroll
            for (int mt = 0; mt < 2; mt++)
#pragma unroll
                for (int nt = 0; nt < NT8; nt++) {
                    MMA16816(acc[mt][nt], ah[mt], bh[nt]);
                    MMA16816(acc[mt][nt], ah[mt], bl[nt]);
                    MMA16816(acc[mt][nt], al[mt], bh[nt]);
                }
        }
        __syncthreads();                     // before next load reuses slot
    }

    const int erow = (lane >> 2);
    const int ecol = (lane & 3) * 2;
#pragma unroll
    for (int mt = 0; mt < 2; mt++) {
#pragma unroll
        for (int nt = 0; nt < NT8; nt++) {
            const int col = col0 + warpN0 + nt * 8 + ecol;
            const float2 b2 = *(const float2*)(bias + col);
#pragma unroll
            for (int h = 0; h < 2; h++) {
                const int row = row0 + warpM0 + mt * 16 + erow + h * 8;
                if (row >= M) continue;
                float vx = acc[mt][nt][2 * h]     + b2.x;
                float vy = acc[mt][nt][2 * h + 1] + b2.y;
                vx = vx >= 0.f ? vx : SLOPE * vx;
                vy = vy >= 0.f ? vy : SLOPE * vy;
                *(float2*)(C + (size_t)row * Nout + col) = make_float2(vx, vy);
            }
        }
    }
}

// ---------------------------------------------------------------------------
// Fused final GEMM: out = leaky(x@Wres+b_res) + leaky(a2@Wfin+b_fin)
// Same quad-tile geometry; two sequential accumulation phases.
// ---------------------------------------------------------------------------
__global__ __launch_bounds__(256, 2) void gemm_fused_final(
    const bf16* __restrict__ xhi, const bf16* __restrict__ xlo,
    const bf16* __restrict__ wrh, const bf16* __restrict__ wrl,
    const float* __restrict__ b_res,
    const bf16* __restrict__ a2hi, const bf16* __restrict__ a2lo,
    const bf16* __restrict__ wfh, const bf16* __restrict__ wfl,
    const float* __restrict__ b_fin,
    float* __restrict__ C, int M)
{
    constexpr int BM = 64, BN = 128, BK = 64, SA = BK + 8;
    constexpr int AT = BM * SA * 2;
    constexpr int BT = BN * SA * 2;
    constexpr int STAGE = 2 * AT + 2 * BT;
    constexpr int NT8 = 4, NPAIR = 2, NCH = 4;

    extern __shared__ __align__(16) char smem[];
    const uint32_t s0 = smem_u32(smem);

    const int tid  = threadIdx.x;
    const int lane = tid & 31;
    const int wid  = tid >> 5;
    const int warpM0 = (wid >> 2) * 32;
    const int warpN0 = (wid & 3) * 32;
    const int row0 = blockIdx.x * BM;
    const int col0 = blockIdx.y * BN;

    const int lr = tid >> 3;
    const int lc = (tid & 7) * 8;

    const uint32_t aOff = ((warpM0 + (lane & 15)) * SA + (lane >> 4) * 8) * 2;
    const uint32_t bOff = ((warpN0 + ((lane >> 4) * 8) + (lane & 7)) * SA
                          + ((lane >> 3) & 1) * 8) * 2;

    float accR[2][NT8][4], accF[2][NT8][4];
#pragma unroll
    for (int mt = 0; mt < 2; mt++)
#pragma unroll
        for (int nt = 0; nt < NT8; nt++)
#pragma unroll
            for (int j = 0; j < 4; j++) { accR[mt][nt][j] = 0.f; accF[mt][nt][j] = 0.f; }

    auto run_phase = [&](float (&acc)[2][NT8][4],
                         const bf16* AH, const bf16* AL,
                         const bf16* BH, const bf16* BL) {
        auto load_chunk = [&](int kc, int slot) {
            const int kbase = kc * BK;
            const uint32_t base = s0 + slot * STAGE;
#pragma unroll
            for (int i = 0; i < 2; i++) {
                int r = lr + 32 * i;
                int gr = row0 + r;
                if (gr > M - 1) gr = M - 1;
                const size_t g = (size_t)gr * 256 + kbase + lc;
                CP16(base + (r * SA + lc) * 2,      AH + g);
                CP16(base + AT + (r * SA + lc) * 2, AL + g);
            }
#pragma unroll
            for (int i = 0; i < 4; i++) {
                int r = lr + 32 * i;
                const size_t g = (size_t)(col0 + r) * 256 + kbase + lc;
                CP16(base + 2 * AT + (r * SA + lc) * 2,      BH + g);
                CP16(base + 2 * AT + BT + (r * SA + lc) * 2, BL + g);
            }
            CP_COMMIT();
        };

        load_chunk(0, 0);
        for (int it = 0; it < NCH; it++) {
            if (it + 1 < NCH) {
                load_chunk(it + 1, (it + 1) & 1);
                CP_WAIT(1);
            } else {
                CP_WAIT(0);
            }
            __syncthreads();

            const uint32_t base = s0 + (it & 1) * STAGE;
            const uint32_t aHi = base + aOff;
            const uint32_t aLo = base + AT + aOff;
            const uint32_t bHi = base + 2 * AT + bOff;
            const uint32_t bLo = base + 2 * AT + BT + bOff;

#pragma unroll
            for (int ks = 0; ks < 4; ks++) {
                uint32_t ah[2][4], al[2][4];
#pragma unroll
                for (int mt = 0; mt < 2; mt++) {
                    LDSM_X4(ah[mt], aHi + mt * (16 * SA * 2) + ks * 32);
                    LDSM_X4(al[mt], aLo + mt * (16 * SA * 2) + ks * 32);
                }
                uint32_t bh[NT8][2], bl[NT8][2];
#pragma unroll
                for (int np = 0; np < NPAIR; np++) {
                    uint32_t t[4];
                    LDSM_X4(t, bHi + np * (16 * SA * 2) + ks * 32);
                    bh[2 * np][0] = t[0]; bh[2 * np][1] = t[1];
                    bh[2 * np + 1][0] = t[2]; bh[2 * np + 1][1] = t[3];
                    LDSM_X4(t, bLo + np * (16 * SA * 2) + ks * 32);
                    bl[2 * np][0] = t[0]; bl[2 * np][1] = t[1];
                    bl[2 * np + 1][0] = t[2]; bl[2 * np + 1][1] = t[3];
                }
#pragma unroll
                for (int mt = 0; mt < 2; mt++)
#pragma unroll
                    for (int nt = 0; nt < NT8; nt++) {
                        MMA16816(acc[mt][nt], ah[mt], bh[nt]);
                        MMA16816(acc[mt][nt], ah[mt], bl[nt]);
                        MMA16816(acc[mt][nt], al[mt], bh[nt]);
                    }
            }
            __syncthreads();
        }
    };

    run_phase(accR, xhi, xlo, wrh, wrl);
    run_phase(accF, a2hi, a2lo, wfh, wfl);

    // epilogue: out = leaky(accR + b_res) + leaky(accF + b_fin)
    const int erow = (lane >> 2);
    const int ecol = (lane & 3) * 2;
#pragma unroll
    for (int mt = 0; mt < 2; mt++) {
#pragma unroll
        for (int nt = 0; nt < NT8; nt++) {
            const int col = col0 + warpN0 + nt * 8 + ecol;
            const float2 br = *(const float2*)(b_res + col);
            const float2 bfi = *(const float2*)(b_fin + col);
#pragma unroll
            for (int h = 0; h < 2; h++) {
                const int row = row0 + warpM0 + mt * 16 + erow + h * 8;
                if (row >= M) continue;
                float rx = accR[mt][nt][2 * h]     + br.x;
                float ry = accR[mt][nt][2 * h + 1] + br.y;
                rx = rx >= 0.f ? rx : SLOPE * rx;
                ry = ry >= 0.f ? ry : SLOPE * ry;
                float fx = accF[mt][nt][2 * h]     + bfi.x;
                float fy = accF[mt][nt][2 * h + 1] + bfi.y;
                fx = fx >= 0.f ? fx : SLOPE * fx;
                fy = fy >= 0.f ? fy : SLOPE * fy;
                *(float2*)(C + (size_t)row * 256 + col) =
                    make_float2(rx + fx, ry + fy);
            }
        }
    }
}

// ---------------------------------------------------------------------------
// LFA1 (D=64, f32 out [N,128]): lane owns 2 cols; one LDG.64 per gathered row.
// 256-thread blocks (measured best: 35.1us vs 40.5us at 512).
// ---------------------------------------------------------------------------
__global__ __launch_bounds__(256) void lfa1_kernel(
    const float* __restrict__ geom, const int* __restrict__ idx,
    const float* __restrict__ feat, float* __restrict__ out,
    const float* __restrict__ wg, const float* __restrict__ bg, int N)
{
    __shared__ float sw[4][64];
    __shared__ float sb[64];
    for (int i = threadIdx.x; i < 4 * 64; i += blockDim.x) sw[i >> 6][i & 63] = wg[i];
    for (int i = threadIdx.x; i < 64; i += blockDim.x) sb[i] = bg[i];
    __syncthreads();

    const int warp = threadIdx.x >> 5;
    const int lane = threadIdx.x & 31;
    const int wpb  = blockDim.x >> 5;
    const int d0   = lane * 2;

    const float2 w0 = *(const float2*)&sw[0][d0];
    const float2 w1 = *(const float2*)&sw[1][d0];
    const float2 w2 = *(const float2*)&sw[2][d0];
    const float2 w3 = *(const float2*)&sw[3][d0];
    const float2 bb = *(const float2*)&sb[d0];
    const float inv = 1.0f / (float)PK;

    for (int n = blockIdx.x * wpb + warp; n < N; n += gridDim.x * wpb) {
        int rows[PK];
        const int4* ip = (const int4*)(idx + (size_t)n * PK);
#pragma unroll
        for (int k4 = 0; k4 < PK / 4; k4++) {
            int4 r = ip[k4];
            rows[4 * k4 + 0] = r.x; rows[4 * k4 + 1] = r.y;
            rows[4 * k4 + 2] = r.z; rows[4 * k4 + 3] = r.w;
        }

        float2 t[PK];
#pragma unroll
        for (int k = 0; k < PK; k++)
            t[k] = *(const float2*)(feat + (size_t)rows[k] * 64 + d0);

        float2 accG = {0.f, 0.f};
        const float4* gp = (const float4*)(geom + (size_t)n * (PK * 4));
#pragma unroll
        for (int k = 0; k < PK; k++) {
            const float4 g = gp[k];
            float vx = bb.x, vy = bb.y;
            vx = fmaf(g.x, w0.x, vx); vy = fmaf(g.x, w0.y, vy);
            vx = fmaf(g.y, w1.x, vx); vy = fmaf(g.y, w1.y, vy);
            vx = fmaf(g.z, w2.x, vx); vy = fmaf(g.z, w2.y, vy);
            vx = fmaf(g.w, w3.x, vx); vy = fmaf(g.w, w3.y, vy);
            vx = vx >= 0.f ? vx : SLOPE * vx;
            vy = vy >= 0.f ? vy : SLOPE * vy;
            accG.x += vx; accG.y += vy;
        }

        float2 accF = {0.f, 0.f};
#pragma unroll
        for (int k = 0; k < PK; k++) { accF.x += t[k].x; accF.y += t[k].y; }

        float* o = out + (size_t)n * 128;
        *(float2*)(o + d0)      = make_float2(accG.x * inv, accG.y * inv);
        *(float2*)(o + 64 + d0) = make_float2(accF.x * inv, accF.y * inv);
    }
}

// ---------------------------------------------------------------------------
// LFA2 (D=128): lane owns 4 cols (LDG.128 per gathered row); writes split bf16.
// ---------------------------------------------------------------------------
__global__ __launch_bounds__(256) void lfa2_split_kernel(
    const float* __restrict__ geom, const int* __restrict__ idx,
    const float* __restrict__ feat, bf16* __restrict__ ohi,
    bf16* __restrict__ olo,
    const float* __restrict__ wg, const float* __restrict__ bg, int N)
{
    __shared__ float sw[4][128];
    __shared__ float sb[128];
    for (int i = threadIdx.x; i < 4 * 128; i += blockDim.x) sw[i >> 7][i & 127] = wg[i];
    for (int i = threadIdx.x; i < 128; i += blockDim.x) sb[i] = bg[i];
    __syncthreads();

    const int warp = threadIdx.x >> 5;
    const int lane = threadIdx.x & 31;
    const int wpb  = blockDim.x >> 5;
    const int d0   = lane * 4;

    const float4 w0 = *(const float4*)&sw[0][d0];
    const float4 w1 = *(const float4*)&sw[1][d0];
    const float4 w2 = *(const float4*)&sw[2][d0];
    const float4 w3 = *(const float4*)&sw[3][d0];
    const float4 bb = *(const float4*)&sb[d0];
    const float inv = 1.0f / (float)PK;

    for (int n = blockIdx.x * wpb + warp; n < N; n += gridDim.x * wpb) {
        int rows[PK];
        const int4* ip = (const int4*)(idx + (size_t)n * PK);
#pragma unroll
        for (int k4 = 0; k4 < PK / 4; k4++) {
            int4 r = ip[k4];
            rows[4 * k4 + 0] = r.x; rows[4 * k4 + 1] = r.y;
            rows[4 * k4 + 2] = r.z; rows[4 * k4 + 3] = r.w;
        }

        float4 accF = {0.f, 0.f, 0.f, 0.f};
#pragma unroll
        for (int kb = 0; kb < PK; kb += 8) {
            float4 t[8];
#pragma unroll
            for (int j = 0; j < 8; j++)
                t[j] = *(const float4*)(feat + (size_t)rows[kb + j] * 128 + d0);
#pragma unroll
            for (int j = 0; j < 8; j++) {
                accF.x += t[j].x; accF.y += t[j].y;
                accF.z += t[j].z; accF.w += t[j].w;
            }
        }

        float4 accG = {0.f, 0.f, 0.f, 0.f};
        const float4* gp = (const float4*)(geom + (size_t)n * (PK * 4));
#pragma unroll
        for (int k = 0; k < PK; k++) {
            const float4 g = gp[k];
            float vx = bb.x, vy = bb.y, vz = bb.z, vw = bb.w;
            vx = fmaf(g.x, w0.x, vx); vy = fmaf(g.x, w0.y, vy);
            vz = fmaf(g.x, w0.z, vz); vw = fmaf(g.x, w0.w, vw);
            vx = fmaf(g.y, w1.x, vx); vy = fmaf(g.y, w1.y, vy);
            vz = fmaf(g.y, w1.z, vz); vw = fmaf(g.y, w1.w, vw);
            vx = fmaf(g.z, w2.x, vx); vy = fmaf(g.z, w2.y, vy);
            vz = fmaf(g.z, w2.z, vz); vw = fmaf(g.z, w2.w, vw);
            vx = fmaf(g.w, w3.x, vx); vy = fmaf(g.w, w3.y, vy);
            vz = fmaf(g.w, w3.z, vz); vw = fmaf(g.w, w3.w, vw);
            vx = vx >= 0.f ? vx : SLOPE * vx;
            vy = vy >= 0.f ? vy : SLOPE * vy;
            vz = vz >= 0.f ? vz : SLOPE * vz;
            vw = vw >= 0.f ? vw : SLOPE * vw;
            accG.x += vx; accG.y += vy; accG.z += vz; accG.w += vw;
        }

        const size_t base = (size_t)n * 256;
        bf16 h0, h1, h2, h3, l0, l1, l2, l3;
        bf16_split(accG.x * inv, h0, l0); bf16_split(accG.y * inv, h1, l1);
        bf16_split(accG.z * inv, h2, l2); bf16_split(accG.w * inv, h3, l3);
        *(uint2*)(ohi + base + d0) = pack4_bf16(h0, h1, h2, h3);
        *(uint2*)(olo + base + d0) = pack4_bf16(l0, l1, l2, l3);
        bf16_split(accF.x * inv, h0, l0); bf16_split(accF.y * inv, h1, l1);
        bf16_split(accF.z * inv, h2, l2); bf16_split(accF.w * inv, h3, l3);
        *(uint2*)(ohi + base + 128 + d0) = pack4_bf16(h0, h1, h2, h3);
        *(uint2*)(olo + base + 128 + d0) = pack4_bf16(l0, l1, l2, l3);
    }
}

// ---------------------------------------------------------------------------
// Launch
// ---------------------------------------------------------------------------
extern "C" void kernel_launch(void* const* d_in, const int* in_sizes, int n_in,
                              void* d_out, int out_size)
{
    const float* x      = (const float*)d_in[0];
    const float* geom   = (const float*)d_in[1];
    const int*   idx    = (const int*)  d_in[2];
    const float* w_res  = (const float*)d_in[3];
    const float* b_res  = (const float*)d_in[4];
    const float* w_init = (const float*)d_in[5];
    const float* b_init = (const float*)d_in[6];
    const float* w_g1   = (const float*)d_in[7];
    const float* b_g1   = (const float*)d_in[8];
    const float* w_g2   = (const float*)d_in[9];
    const float* b_g2   = (const float*)d_in[10];
    const float* w_fin  = (const float*)d_in[11];
    const float* b_fin  = (const float*)d_in[12];
    float* out = (float*)d_out;

    float *a0, *a1;
    bf16 *xhi, *xlo, *a2hi, *a2lo;
    bf16 *wres_hi, *wres_lo, *winit_hi, *winit_lo, *wfin_hi, *wfin_lo;
    cudaGetSymbolAddress((void**)&a0, g_a0);
    cudaGetSymbolAddress((void**)&a1, g_a1);
    cudaGetSymbolAddress((void**)&xhi, g_xhi);
    cudaGetSymbolAddress((void**)&xlo, g_xlo);
    cudaGetSymbolAddress((void**)&a2hi, g_a2hi);
    cudaGetSymbolAddress((void**)&a2lo, g_a2lo);
    cudaGetSymbolAddress((void**)&wres_hi, g_wres_hi);
    cudaGetSymbolAddress((void**)&wres_lo, g_wres_lo);
    cudaGetSymbolAddress((void**)&winit_hi, g_winit_hi);
    cudaGetSymbolAddress((void**)&winit_lo, g_winit_lo);
    cudaGetSymbolAddress((void**)&wfin_hi, g_wfin_hi);
    cudaGetSymbolAddress((void**)&wfin_lo, g_wfin_lo);

    // 2-stage quad-tile smem:
    //   BN=128: 2*(2*9216 + 2*18432) = 110592 B ; x2 CTA/SM = 221184 B (fits)
    //   BN=64 : 2*(2*9216 + 2*9216)  =  73728 B
    constexpr int SMEM128 = 2 * (2 * 64 * 72 * 2 + 2 * 128 * 72 * 2);
    constexpr int SMEM64  = 2 * (2 * 64 * 72 * 2 + 2 * 64 * 72 * 2);
    cudaFuncSetAttribute(gemm_fused_final, cudaFuncAttributeMaxDynamicSharedMemorySize, SMEM128);
    cudaFuncSetAttribute(gemm_mma<64>, cudaFuncAttributeMaxDynamicSharedMemorySize, SMEM64);

    const int M = PN;
    const int mTiles = (M + 63) / 64;               // 782
    const int lfaBlocks = (M + 7) / 8;              // 6250 (8 warps/block)

    // prep: split inputs / weights into bf16 hi+lo
    const int n4 = M * PDIM / 4;
    split_x_kernel<<<(n4 + 255) / 256, 256>>>(x, xhi, xlo, n4);
    prep_weights<<<(147456 + 255) / 256, 256>>>(w_res, w_init, w_fin,
                                                wres_hi, wres_lo,
                                                winit_hi, winit_lo,
                                                wfin_hi, wfin_lo);

    // 1) a0 = leaky(x @ w_init + b)
    gemm_mma<64><<<dim3(mTiles, 1), 256, SMEM64>>>(
        xhi, xlo, winit_hi, winit_lo, b_init, a0, M, 64);
    // 2) LFA1 -> a1 [N,128]
    lfa1_kernel<<<lfaBlocks, 256>>>(geom, idx, a0, a1, w_g1, b_g1, M);
    // 3) LFA2 -> a2 split bf16 [N,256]
    lfa2_split_kernel<<<lfaBlocks, 256>>>(geom, idx, a1, a2hi, a2lo, w_g2, b_g2, M);
    // 4) out = leaky(x@w_res+b_res) + leaky(a2@w_fin+b_fin)  (un-poisons d_out)
    gemm_fused_final<<<dim3(mTiles, 2), 256, SMEM128>>>(
        xhi, xlo, wres_hi, wres_lo, b_res,
        a2hi, a2lo, wfin_hi, wfin_lo, b_fin, out, M);
}

// round 13
// speedup vs baseline: 1.2456x; 1.0243x over previous
#include <cuda_runtime.h>
#include <cuda_bf16.h>
#include <cstdint>
#include <cstddef>

// Problem constants (ResidualBlock: N=50000, K=16, DIM=256, LeakyReLU slope 0.2)
#define PN    50000
#define PK    16
#define PDIM  256
#define SLOPE 0.2f

typedef __nv_bfloat16 bf16;

// ---------------------------------------------------------------------------
// Scratch (__device__ globals; no allocations allowed)
// ---------------------------------------------------------------------------
__device__ __align__(16) float g_a0[(size_t)PN * 64];     // init MLP out [N,64]
__device__ __align__(16) float g_a1[(size_t)PN * 128];    // LFA1 out     [N,128]
__device__ __align__(16) bf16 g_a2hi[(size_t)PN * 256];
__device__ __align__(16) bf16 g_a2lo[(size_t)PN * 256];
__device__ __align__(16) bf16 g_wres_hi[256 * 256];   // transposed: [n][k]
__device__ __align__(16) bf16 g_wres_lo[256 * 256];
__device__ __align__(16) bf16 g_winit_hi[64 * 256];
__device__ __align__(16) bf16 g_winit_lo[64 * 256];
__device__ __align__(16) bf16 g_wfin_hi[256 * 256];
__device__ __align__(16) bf16 g_wfin_lo[256 * 256];

// ---------------------------------------------------------------------------
// PTX helpers (all plain-sm_103-legal: cp.async, ldmatrix, mma.sync)
// ---------------------------------------------------------------------------
__device__ __forceinline__ uint32_t smem_u32(const void* p) {
    uint32_t a;
    asm("{ .reg .u64 t; cvta.to.shared.u64 t, %1; cvt.u32.u64 %0, t; }"
        : "=r"(a) : "l"(p));
    return a;
}

#define CP16(dst, src) \
    asm volatile("cp.async.cg.shared.global [%0], [%1], 16;" \
                 :: "r"(dst), "l"(src) : "memory")
#define CP_COMMIT() asm volatile("cp.async.commit_group;" ::: "memory")
#define CP_WAIT(n)  asm volatile("cp.async.wait_group %0;" :: "n"(n) : "memory")

#define LDSM_X4(r, addr) \
    asm volatile("ldmatrix.sync.aligned.m8n8.x4.shared.b16 {%0,%1,%2,%3}, [%4];" \
                 : "=r"((r)[0]), "=r"((r)[1]), "=r"((r)[2]), "=r"((r)[3]) \
                 : "r"(addr))

#define MMA16816(d, a, b) \
    asm volatile("mma.sync.aligned.m16n8k16.row.col.f32.bf16.bf16.f32 " \
                 "{%0,%1,%2,%3},{%4,%5,%6,%7},{%8,%9},{%0,%1,%2,%3};" \
                 : "+f"((d)[0]), "+f"((d)[1]), "+f"((d)[2]), "+f"((d)[3]) \
                 : "r"((a)[0]), "r"((a)[1]), "r"((a)[2]), "r"((a)[3]), \
                   "r"((b)[0]), "r"((b)[1]))

// ---------------------------------------------------------------------------
// bf16 hi/lo split helpers
// ---------------------------------------------------------------------------
__device__ __forceinline__ void bf16_split(float v, bf16& h, bf16& l)
{
    h = __float2bfloat16(v);
    l = __float2bfloat16(v - __bfloat162float(h));
}

__device__ __forceinline__ uint2 pack4_bf16(bf16 a, bf16 b, bf16 c, bf16 d)
{
    __nv_bfloat162 p0 = {a, b}, p1 = {c, d};
    uint2 r;
    r.x = *(uint32_t*)&p0;
    r.y = *(uint32_t*)&p1;
    return r;
}

// Convert 8 f32 (two float4) -> 8 hi bf16 (uint4) + 8 lo bf16 (uint4)
__device__ __forceinline__ void split8(const float4 a, const float4 b,
                                       uint4& hv, uint4& lv)
{
    bf16 h[8], l[8];
    bf16_split(a.x, h[0], l[0]); bf16_split(a.y, h[1], l[1]);
    bf16_split(a.z, h[2], l[2]); bf16_split(a.w, h[3], l[3]);
    bf16_split(b.x, h[4], l[4]); bf16_split(b.y, h[5], l[5]);
    bf16_split(b.z, h[6], l[6]); bf16_split(b.w, h[7], l[7]);
    uint2 p0 = pack4_bf16(h[0], h[1], h[2], h[3]);
    uint2 p1 = pack4_bf16(h[4], h[5], h[6], h[7]);
    hv = make_uint4(p0.x, p0.y, p1.x, p1.y);
    p0 = pack4_bf16(l[0], l[1], l[2], l[3]);
    p1 = pack4_bf16(l[4], l[5], l[6], l[7]);
    lv = make_uint4(p0.x, p0.y, p1.x, p1.y);
}

// All three weights: W[K=256, Ncols] f32 -> transposed split bf16 Wt[Ncols][256]
__global__ __launch_bounds__(256) void prep_weights(
    const float* __restrict__ w_res, const float* __restrict__ w_init,
    const float* __restrict__ w_fin,
    bf16* __restrict__ rh, bf16* __restrict__ rl,
    bf16* __restrict__ ih, bf16* __restrict__ il,
    bf16* __restrict__ fh, bf16* __restrict__ fl)
{
    int i = blockIdx.x * blockDim.x + threadIdx.x;
    bf16 h, l;
    if (i < 65536) {                                  // w_res [256,256]
        int n = i >> 8, k = i & 255;
        bf16_split(w_res[(size_t)k * 256 + n], h, l);
        rh[i] = h; rl[i] = l;
    } else if (i < 81920) {                           // w_init [256,64]
        int j = i - 65536;
        int n = j >> 8, k = j & 255;
        bf16_split(w_init[(size_t)k * 64 + n], h, l);
        ih[j] = h; il[j] = l;
    } else if (i < 147456) {                          // w_fin [256,256]
        int j = i - 81920;
        int n = j >> 8, k = j & 255;
        bf16_split(w_fin[(size_t)k * 256 + n], h, l);
        fh[j] = h; fl[j] = l;
    }
}

// ---------------------------------------------------------------------------
// Quad-tile HMMA GEMM, A read as f32 and split in-kernel during staging
// (LDG f32 prefetched one chunk ahead -> CVT -> STS hi/lo; B via cp.async).
// Per 64-wide k-chunk: one residency, three split products (ah*bh+ah*bl+al*bh).
// CTA: BM=64 x BN, 256 threads, warp grid 2(M) x 4(N); 2 CTAs/SM.
// ---------------------------------------------------------------------------
template <int BN>
__global__ __launch_bounds__(256, 2) void gemm_mma_f32a(
    const float* __restrict__ Ax,
    const bf16* __restrict__ Bhi, const bf16* __restrict__ Blo,
    const float* __restrict__ bias, float* __restrict__ C, int M, int Nout)
{
    constexpr int BM = 64, BK = 64, SA = BK + 8;
    constexpr int AT = BM * SA * 2;          // one A split tile (9216 B)
    constexpr int BT = BN * SA * 2;
    constexpr int STAGE = 2 * AT + 2 * BT;   // Ah | Al | Bh | Bl
    constexpr int NT8 = BN / 32;
    constexpr int NPAIR = NT8 / 2;
    constexpr int NCH = 4;

    extern __shared__ __align__(16) char smem[];
    const uint32_t s0 = smem_u32(smem);

    const int tid  = threadIdx.x;
    const int lane = tid & 31;
    const int wid  = tid >> 5;
    const int warpM0 = (wid >> 2) * 32;
    const int warpN0 = (wid & 3) * (BN / 4);
    const int row0 = blockIdx.x * BM;
    const int col0 = blockIdx.y * BN;

    const int lr = tid >> 3;                 // 0..31
    const int lc = (tid & 7) * 8;

    float acc[2][NT8][4];
#pragma unroll
    for (int mt = 0; mt < 2; mt++)
#pragma unroll
        for (int nt = 0; nt < NT8; nt++)
#pragma unroll
            for (int j = 0; j < 4; j++) acc[mt][nt][j] = 0.f;

    auto ldg_A = [&](int kc, float4 (&v)[4]) {
        const int kbase = kc * BK;
#pragma unroll
        for (int i = 0; i < 2; i++) {
            int gr = row0 + lr + 32 * i;
            if (gr > M - 1) gr = M - 1;
            const float* p = Ax + (size_t)gr * 256 + kbase + lc;
            v[2 * i]     = *(const float4*)p;
            v[2 * i + 1] = *(const float4*)(p + 4);
        }
    };
    auto sts_A = [&](const float4 (&v)[4], int slot) {
#pragma unroll
        for (int i = 0; i < 2; i++) {
            const int r = lr + 32 * i;
            uint4 hv, lv;
            split8(v[2 * i], v[2 * i + 1], hv, lv);
            char* dst = smem + slot * STAGE + (r * SA + lc) * 2;
            *(uint4*)dst        = hv;
            *(uint4*)(dst + AT) = lv;
        }
    };
    auto load_B = [&](int kc, int slot) {
        const int kbase = kc * BK;
        const uint32_t base = s0 + slot * STAGE + 2 * AT;
#pragma unroll
        for (int i = 0; i < BN / 32; i++) {
            int r = lr + 32 * i;
            const size_t g = (size_t)(col0 + r) * 256 + kbase + lc;
            CP16(base + (r * SA + lc) * 2,      Bhi + g);
            CP16(base + BT + (r * SA + lc) * 2, Blo + g);
        }
        CP_COMMIT();
    };

    // prologue
    float4 rA[4];
    ldg_A(0, rA);
    sts_A(rA, 0);
    load_B(0, 0);
    ldg_A(1, rA);

    const uint32_t aOff = ((warpM0 + (lane & 15)) * SA + (lane >> 4) * 8) * 2;
    const uint32_t bOff = ((warpN0 + ((lane >> 4) * 8) + (lane & 7)) * SA
                          + ((lane >> 3) & 1) * 8) * 2;

    for (int it = 0; it < NCH; it++) {
        if (it + 1 < NCH) {
            sts_A(rA, (it + 1) & 1);
            load_B(it + 1, (it + 1) & 1);
            if (it + 2 < NCH) ldg_A(it + 2, rA);
            CP_WAIT(1);                      // chunk `it` B resident
        } else {
            CP_WAIT(0);                      // tail: all groups complete
        }
        __syncthreads();

        const uint32_t base = s0 + (it & 1) * STAGE;
        const uint32_t aHi = base + aOff;
        const uint32_t aLo = base + AT + aOff;
        const uint32_t bHi = base + 2 * AT + bOff;
        const uint32_t bLo = base + 2 * AT + BT + bOff;

#pragma unroll
        for (int ks = 0; ks < 4; ks++) {
            uint32_t ah[2][4], al[2][4];
#pragma unroll
            for (int mt = 0; mt < 2; mt++) {
                LDSM_X4(ah[mt], aHi + mt * (16 * SA * 2) + ks * 32);
                LDSM_X4(al[mt], aLo + mt * (16 * SA * 2) + ks * 32);
            }
            uint32_t bh[NT8][2], bl[NT8][2];
#pragma unroll
            for (int np = 0; np < NPAIR; np++) {
                uint32_t t[4];
                LDSM_X4(t, bHi + np * (16 * SA * 2) + ks * 32);
                bh[2 * np][0] = t[0]; bh[2 * np][1] = t[1];
                bh[2 * np + 1][0] = t[2]; bh[2 * np + 1][1] = t[3];
                LDSM_X4(t, bLo + np * (16 * SA * 2) + ks * 32);
                bl[2 * np][0] = t[0]; bl[2 * np][1] = t[1];
                bl[2 * np + 1][0] = t[2]; bl[2 * np + 1][1] = t[3];
            }
#pragma unroll
            for (int mt = 0; mt < 2; mt++)
#pragma unroll
                for (int nt = 0; nt < NT8; nt++) {
                    MMA16816(acc[mt][nt], ah[mt], bh[nt]);
                    MMA16816(acc[mt][nt], ah[mt], bl[nt]);
                    MMA16816(acc[mt][nt], al[mt], bh[nt]);
                }
        }
        __syncthreads();                     // slot safe for reuse
    }

    const int erow = (lane >> 2);
    const int ecol = (lane & 3) * 2;
#pragma unroll
    for (int mt = 0; mt < 2; mt++) {
#pragma unroll
        for (int nt = 0; nt < NT8; nt++) {
            const int col = col0 + warpN0 + nt * 8 + ecol;
            const float2 b2 = *(const float2*)(bias + col);
#pragma unroll
            for (int h = 0; h < 2; h++) {
                const int row = row0 + warpM0 + mt * 16 + erow + h * 8;
                if (row >= M) continue;
                float vx = acc[mt][nt][2 * h]     + b2.x;
                float vy = acc[mt][nt][2 * h + 1] + b2.y;
                vx = vx >= 0.f ? vx : SLOPE * vx;
                vy = vy >= 0.f ? vy : SLOPE * vy;
                *(float2*)(C + (size_t)row * Nout + col) = make_float2(vx, vy);
            }
        }
    }
}

// ---------------------------------------------------------------------------
// Fused final GEMM: out = leaky(x@Wres+b_res) + leaky(a2@Wfin+b_fin)
// Phase 1: A = x f32 (in-kernel split); Phase 2: A = a2 bf16 split (cp.async).
// ---------------------------------------------------------------------------
__global__ __launch_bounds__(256, 2) void gemm_fused_final(
    const float* __restrict__ x,
    const bf16* __restrict__ wrh, const bf16* __restrict__ wrl,
    const float* __restrict__ b_res,
    const bf16* __restrict__ a2hi, const bf16* __restrict__ a2lo,
    const bf16* __restrict__ wfh, const bf16* __restrict__ wfl,
    const float* __restrict__ b_fin,
    float* __restrict__ C, int M)
{
    constexpr int BM = 64, BN = 128, BK = 64, SA = BK + 8;
    constexpr int AT = BM * SA * 2;
    constexpr int BT = BN * SA * 2;
    constexpr int STAGE = 2 * AT + 2 * BT;
    constexpr int NT8 = 4, NPAIR = 2, NCH = 4;

    extern __shared__ __align__(16) char smem[];
    const uint32_t s0 = smem_u32(smem);

    const int tid  = threadIdx.x;
    const int lane = tid & 31;
    const int wid  = tid >> 5;
    const int warpM0 = (wid >> 2) * 32;
    const int warpN0 = (wid & 3) * 32;
    const int row0 = blockIdx.x * BM;
    const int col0 = blockIdx.y * BN;

    const int lr = tid >> 3;
    const int lc = (tid & 7) * 8;

    const uint32_t aOff = ((warpM0 + (lane & 15)) * SA + (lane >> 4) * 8) * 2;
    const uint32_t bOff = ((warpN0 + ((lane >> 4) * 8) + (lane & 7)) * SA
                          + ((lane >> 3) & 1) * 8) * 2;

    float accR[2][NT8][4], accF[2][NT8][4];
#pragma unroll
    for (int mt = 0; mt < 2; mt++)
#pragma unroll
        for (int nt = 0; nt < NT8; nt++)
#pragma unroll
            for (int j = 0; j < 4; j++) { accR[mt][nt][j] = 0.f; accF[mt][nt][j] = 0.f; }

    auto run_phase = [&](float (&acc)[2][NT8][4], const float* Af,
                         const bf16* AH, const bf16* AL,
                         const bf16* BH, const bf16* BL) {
        auto ldg_A = [&](int kc, float4 (&v)[4]) {
            const int kbase = kc * BK;
#pragma unroll
            for (int i = 0; i < 2; i++) {
                int gr = row0 + lr + 32 * i;
                if (gr > M - 1) gr = M - 1;
                const float* p = Af + (size_t)gr * 256 + kbase + lc;
                v[2 * i]     = *(const float4*)p;
                v[2 * i + 1] = *(const float4*)(p + 4);
            }
        };
        auto sts_A = [&](const float4 (&v)[4], int slot) {
#pragma unroll
            for (int i = 0; i < 2; i++) {
                const int r = lr + 32 * i;
                uint4 hv, lv;
                split8(v[2 * i], v[2 * i + 1], hv, lv);
                char* dst = smem + slot * STAGE + (r * SA + lc) * 2;
                *(uint4*)dst        = hv;
                *(uint4*)(dst + AT) = lv;
            }
        };
        auto cp_A = [&](int kc, int slot) {
            const int kbase = kc * BK;
            const uint32_t base = s0 + slot * STAGE;
#pragma unroll
            for (int i = 0; i < 2; i++) {
                int r = lr + 32 * i;
                int gr = row0 + r;
                if (gr > M - 1) gr = M - 1;
                const size_t g = (size_t)gr * 256 + kbase + lc;
                CP16(base + (r * SA + lc) * 2,      AH + g);
                CP16(base + AT + (r * SA + lc) * 2, AL + g);
            }
        };
        auto load_B = [&](int kc, int slot) {
            const int kbase = kc * BK;
            const uint32_t base = s0 + slot * STAGE + 2 * AT;
#pragma unroll
            for (int i = 0; i < 4; i++) {
                int r = lr + 32 * i;
                const size_t g = (size_t)(col0 + r) * 256 + kbase + lc;
                CP16(base + (r * SA + lc) * 2,      BH + g);
                CP16(base + BT + (r * SA + lc) * 2, BL + g);
            }
        };

        const bool f32a = (Af != nullptr);
        float4 rA[4];

        // prologue: stage chunk 0, prefetch chunk 1's A if f32 path
        if (f32a) {
            ldg_A(0, rA);
            sts_A(rA, 0);
            load_B(0, 0);
            CP_COMMIT();
            ldg_A(1, rA);
        } else {
            cp_A(0, 0);
            load_B(0, 0);
            CP_COMMIT();
        }

        for (int it = 0; it < NCH; it++) {
            if (it + 1 < NCH) {
                const int slot = (it + 1) & 1;
                if (f32a) {
                    sts_A(rA, slot);
                    load_B(it + 1, slot);
                    CP_COMMIT();
                    if (it + 2 < NCH) ldg_A(it + 2, rA);
                } else {
                    cp_A(it + 1, slot);
                    load_B(it + 1, slot);
                    CP_COMMIT();
                }
                CP_WAIT(1);
            } else {
                CP_WAIT(0);
            }
            __syncthreads();

            const uint32_t base = s0 + (it & 1) * STAGE;
            const uint32_t aHi = base + aOff;
            const uint32_t aLo = base + AT + aOff;
            const uint32_t bHi = base + 2 * AT + bOff;
            const uint32_t bLo = base + 2 * AT + BT + bOff;

#pragma unroll
            for (int ks = 0; ks < 4; ks++) {
                uint32_t ah[2][4], al[2][4];
#pragma unroll
                for (int mt = 0; mt < 2; mt++) {
                    LDSM_X4(ah[mt], aHi + mt * (16 * SA * 2) + ks * 32);
                    LDSM_X4(al[mt], aLo + mt * (16 * SA * 2) + ks * 32);
                }
                uint32_t bh[NT8][2], bl[NT8][2];
#pragma unroll
                for (int np = 0; np < NPAIR; np++) {
                    uint32_t t[4];
                    LDSM_X4(t, bHi + np * (16 * SA * 2) + ks * 32);
                    bh[2 * np][0] = t[0]; bh[2 * np][1] = t[1];
                    bh[2 * np + 1][0] = t[2]; bh[2 * np + 1][1] = t[3];
                    LDSM_X4(t, bLo + np * (16 * SA * 2) + ks * 32);
                    bl[2 * np][0] = t[0]; bl[2 * np][1] = t[1];
                    bl[2 * np + 1][0] = t[2]; bl[2 * np + 1][1] = t[3];
                }
#pragma unroll
                for (int mt = 0; mt < 2; mt++)
#pragma unroll
                    for (int nt = 0; nt < NT8; nt++) {
                        MMA16816(acc[mt][nt], ah[mt], bh[nt]);
                        MMA16816(acc[mt][nt], ah[mt], bl[nt]);
                        MMA16816(acc[mt][nt], al[mt], bh[nt]);
                    }
            }
            __syncthreads();
        }
    };

    run_phase(accR, x, nullptr, nullptr, wrh, wrl);
    run_phase(accF, nullptr, a2hi, a2lo, wfh, wfl);

    // epilogue: out = leaky(accR + b_res) + leaky(accF + b_fin)
    const int erow = (lane >> 2);
    const int ecol = (lane & 3) * 2;
#pragma unroll
    for (int mt = 0; mt < 2; mt++) {
#pragma unroll
        for (int nt = 0; nt < NT8; nt++) {
            const int col = col0 + warpN0 + nt * 8 + ecol;
            const float2 br = *(const float2*)(b_res + col);
            const float2 bfi = *(const float2*)(b_fin + col);
#pragma unroll
            for (int h = 0; h < 2; h++) {
                const int row = row0 + warpM0 + mt * 16 + erow + h * 8;
                if (row >= M) continue;
                float rx = accR[mt][nt][2 * h]     + br.x;
                float ry = accR[mt][nt][2 * h + 1] + br.y;
                rx = rx >= 0.f ? rx : SLOPE * rx;
                ry = ry >= 0.f ? ry : SLOPE * ry;
                float fx = accF[mt][nt][2 * h]     + bfi.x;
                float fy = accF[mt][nt][2 * h + 1] + bfi.y;
                fx = fx >= 0.f ? fx : SLOPE * fx;
                fy = fy >= 0.f ? fy : SLOPE * fy;
                *(float2*)(C + (size_t)row * 256 + col) =
                    make_float2(rx + fx, ry + fy);
            }
        }
    }
}

// ---------------------------------------------------------------------------
// LFA1 (D=64, f32 out [N,128]): lane owns 2 cols; one LDG.64 per gathered row.
// 256-thread blocks (measured best: 35.1us vs 40.5us at 512).
// ---------------------------------------------------------------------------
__global__ __launch_bounds__(256) void lfa1_kernel(
    const float* __restrict__ geom, const int* __restrict__ idx,
    const float* __restrict__ feat, float* __restrict__ out,
    const float* __restrict__ wg, const float* __restrict__ bg, int N)
{
    __shared__ float sw[4][64];
    __shared__ float sb[64];
    for (int i = threadIdx.x; i < 4 * 64; i += blockDim.x) sw[i >> 6][i & 63] = wg[i];
    for (int i = threadIdx.x; i < 64; i += blockDim.x) sb[i] = bg[i];
    __syncthreads();

    const int warp = threadIdx.x >> 5;
    const int lane = threadIdx.x & 31;
    const int wpb  = blockDim.x >> 5;
    const int d0   = lane * 2;

    const float2 w0 = *(const float2*)&sw[0][d0];
    const float2 w1 = *(const float2*)&sw[1][d0];
    const float2 w2 = *(const float2*)&sw[2][d0];
    const float2 w3 = *(const float2*)&sw[3][d0];
    const float2 bb = *(const float2*)&sb[d0];
    const float inv = 1.0f / (float)PK;

    for (int n = blockIdx.x * wpb + warp; n < N; n += gridDim.x * wpb) {
        int rows[PK];
        const int4* ip = (const int4*)(idx + (size_t)n * PK);
#pragma unroll
        for (int k4 = 0; k4 < PK / 4; k4++) {
            int4 r = ip[k4];
            rows[4 * k4 + 0] = r.x; rows[4 * k4 + 1] = r.y;
            rows[4 * k4 + 2] = r.z; rows[4 * k4 + 3] = r.w;
        }

        float2 t[PK];
#pragma unroll
        for (int k = 0; k < PK; k++)
            t[k] = *(const float2*)(feat + (size_t)rows[k] * 64 + d0);

        float2 accG = {0.f, 0.f};
        const float4* gp = (const float4*)(geom + (size_t)n * (PK * 4));
#pragma unroll
        for (int k = 0; k < PK; k++) {
            const float4 g = gp[k];
            float vx = bb.x, vy = bb.y;
            vx = fmaf(g.x, w0.x, vx); vy = fmaf(g.x, w0.y, vy);
            vx = fmaf(g.y, w1.x, vx); vy = fmaf(g.y, w1.y, vy);
            vx = fmaf(g.z, w2.x, vx); vy = fmaf(g.z, w2.y, vy);
            vx = fmaf(g.w, w3.x, vx); vy = fmaf(g.w, w3.y, vy);
            vx = vx >= 0.f ? vx : SLOPE * vx;
            vy = vy >= 0.f ? vy : SLOPE * vy;
            accG.x += vx; accG.y += vy;
        }

        float2 accF = {0.f, 0.f};
#pragma unroll
        for (int k = 0; k < PK; k++) { accF.x += t[k].x; accF.y += t[k].y; }

        float* o = out + (size_t)n * 128;
        *(float2*)(o + d0)      = make_float2(accG.x * inv, accG.y * inv);
        *(float2*)(o + 64 + d0) = make_float2(accF.x * inv, accF.y * inv);
    }
}

// ---------------------------------------------------------------------------
// LFA2 (D=128): lane owns 4 cols (LDG.128 per gathered row); writes split bf16.
// ---------------------------------------------------------------------------
__global__ __launch_bounds__(256) void lfa2_split_kernel(
    const float* __restrict__ geom, const int* __restrict__ idx,
    const float* __restrict__ feat, bf16* __restrict__ ohi,
    bf16* __restrict__ olo,
    const float* __restrict__ wg, const float* __restrict__ bg, int N)
{
    __shared__ float sw[4][128];
    __shared__ float sb[128];
    for (int i = threadIdx.x; i < 4 * 128; i += blockDim.x) sw[i >> 7][i & 127] = wg[i];
    for (int i = threadIdx.x; i < 128; i += blockDim.x) sb[i] = bg[i];
    __syncthreads();

    const int warp = threadIdx.x >> 5;
    const int lane = threadIdx.x & 31;
    const int wpb  = blockDim.x >> 5;
    const int d0   = lane * 4;

    const float4 w0 = *(const float4*)&sw[0][d0];
    const float4 w1 = *(const float4*)&sw[1][d0];
    const float4 w2 = *(const float4*)&sw[2][d0];
    const float4 w3 = *(const float4*)&sw[3][d0];
    const float4 bb = *(const float4*)&sb[d0];
    const float inv = 1.0f / (float)PK;

    for (int n = blockIdx.x * wpb + warp; n < N; n += gridDim.x * wpb) {
        int rows[PK];
        const int4* ip = (const int4*)(idx + (size_t)n * PK);
#pragma unroll
        for (int k4 = 0; k4 < PK / 4; k4++) {
            int4 r = ip[k4];
            rows[4 * k4 + 0] = r.x; rows[4 * k4 + 1] = r.y;
            rows[4 * k4 + 2] = r.z; rows[4 * k4 + 3] = r.w;
        }

        float4 accF = {0.f, 0.f, 0.f, 0.f};
#pragma unroll
        for (int kb = 0; kb < PK; kb += 8) {
            float4 t[8];
#pragma unroll
            for (int j = 0; j < 8; j++)
                t[j] = *(const float4*)(feat + (size_t)rows[kb + j] * 128 + d0);
#pragma unroll
            for (int j = 0; j < 8; j++) {
                accF.x += t[j].x; accF.y += t[j].y;
                accF.z += t[j].z; accF.w += t[j].w;
            }
        }

        float4 accG = {0.f, 0.f, 0.f, 0.f};
        const float4* gp = (const float4*)(geom + (size_t)n * (PK * 4));
#pragma unroll
        for (int k = 0; k < PK; k++) {
            const float4 g = gp[k];
            float vx = bb.x, vy = bb.y, vz = bb.z, vw = bb.w;
            vx = fmaf(g.x, w0.x, vx); vy = fmaf(g.x, w0.y, vy);
            vz = fmaf(g.x, w0.z, vz); vw = fmaf(g.x, w0.w, vw);
            vx = fmaf(g.y, w1.x, vx); vy = fmaf(g.y, w1.y, vy);
            vz = fmaf(g.y, w1.z, vz); vw = fmaf(g.y, w1.w, vw);
            vx = fmaf(g.z, w2.x, vx); vy = fmaf(g.z, w2.y, vy);
            vz = fmaf(g.z, w2.z, vz); vw = fmaf(g.z, w2.w, vw);
            vx = fmaf(g.w, w3.x, vx); vy = fmaf(g.w, w3.y, vy);
            vz = fmaf(g.w, w3.z, vz); vw = fmaf(g.w, w3.w, vw);
            vx = vx >= 0.f ? vx : SLOPE * vx;
            vy = vy >= 0.f ? vy : SLOPE * vy;
            vz = vz >= 0.f ? vz : SLOPE * vz;
            vw = vw >= 0.f ? vw : SLOPE * vw;
            accG.x += vx; accG.y += vy; accG.z += vz; accG.w += vw;
        }

        const size_t base = (size_t)n * 256;
        bf16 h0, h1, h2, h3, l0, l1, l2, l3;
        bf16_split(accG.x * inv, h0, l0); bf16_split(accG.y * inv, h1, l1);
        bf16_split(accG.z * inv, h2, l2); bf16_split(accG.w * inv, h3, l3);
        *(uint2*)(ohi + base + d0) = pack4_bf16(h0, h1, h2, h3);
        *(uint2*)(olo + base + d0) = pack4_bf16(l0, l1, l2, l3);
        bf16_split(accF.x * inv, h0, l0); bf16_split(accF.y * inv, h1, l1);
        bf16_split(accF.z * inv, h2, l2); bf16_split(accF.w * inv, h3, l3);
        *(uint2*)(ohi + base + 128 + d0) = pack4_bf16(h0, h1, h2, h3);
        *(uint2*)(olo + base + 128 + d0) = pack4_bf16(l0, l1, l2, l3);
    }
}

// ---------------------------------------------------------------------------
// Launch
// ---------------------------------------------------------------------------
extern "C" void kernel_launch(void* const* d_in, const int* in_sizes, int n_in,
                              void* d_out, int out_size)
{
    const float* x      = (const float*)d_in[0];
    const float* geom   = (const float*)d_in[1];
    const int*   idx    = (const int*)  d_in[2];
    const float* w_res  = (const float*)d_in[3];
    const float* b_res  = (const float*)d_in[4];
    const float* w_init = (const float*)d_in[5];
    const float* b_init = (const float*)d_in[6];
    const float* w_g1   = (const float*)d_in[7];
    const float* b_g1   = (const float*)d_in[8];
    const float* w_g2   = (const float*)d_in[9];
    const float* b_g2   = (const float*)d_in[10];
    const float* w_fin  = (const float*)d_in[11];
    const float* b_fin  = (const float*)d_in[12];
    float* out = (float*)d_out;

    float *a0, *a1;
    bf16 *a2hi, *a2lo;
    bf16 *wres_hi, *wres_lo, *winit_hi, *winit_lo, *wfin_hi, *wfin_lo;
    cudaGetSymbolAddress((void**)&a0, g_a0);
    cudaGetSymbolAddress((void**)&a1, g_a1);
    cudaGetSymbolAddress((void**)&a2hi, g_a2hi);
    cudaGetSymbolAddress((void**)&a2lo, g_a2lo);
    cudaGetSymbolAddress((void**)&wres_hi, g_wres_hi);
    cudaGetSymbolAddress((void**)&wres_lo, g_wres_lo);
    cudaGetSymbolAddress((void**)&winit_hi, g_winit_hi);
    cudaGetSymbolAddress((void**)&winit_lo, g_winit_lo);
    cudaGetSymbolAddress((void**)&wfin_hi, g_wfin_hi);
    cudaGetSymbolAddress((void**)&wfin_lo, g_wfin_lo);

    // 2-stage quad-tile smem (unchanged layout):
    //   BN=128: 2*(2*9216 + 2*18432) = 110592 B ; x2 CTA/SM fits 228KB
    //   BN=64 : 2*(2*9216 + 2*9216)  =  73728 B
    constexpr int SMEM128 = 2 * (2 * 64 * 72 * 2 + 2 * 128 * 72 * 2);
    constexpr int SMEM64  = 2 * (2 * 64 * 72 * 2 + 2 * 64 * 72 * 2);
    cudaFuncSetAttribute(gemm_fused_final, cudaFuncAttributeMaxDynamicSharedMemorySize, SMEM128);
    cudaFuncSetAttribute(gemm_mma_f32a<64>, cudaFuncAttributeMaxDynamicSharedMemorySize, SMEM64);

    const int M = PN;
    const int mTiles = (M + 63) / 64;               // 782
    const int lfaBlocks = (M + 7) / 8;              // 6250 (8 warps/block)

    // prep: weights -> transposed bf16 hi/lo (x is split in-GEMM now)
    prep_weights<<<(147456 + 255) / 256, 256>>>(w_res, w_init, w_fin,
                                                wres_hi, wres_lo,
                                                winit_hi, winit_lo,
                                                wfin_hi, wfin_lo);

    // 1) a0 = leaky(x @ w_init + b)   (A = x f32, split in-kernel)
    gemm_mma_f32a<64><<<dim3(mTiles, 1), 256, SMEM64>>>(
        x, winit_hi, winit_lo, b_init, a0, M, 64);
    // 2) LFA1 -> a1 [N,128]
    lfa1_kernel<<<lfaBlocks, 256>>>(geom, idx, a0, a1, w_g1, b_g1, M);
    // 3) LFA2 -> a2 split bf16 [N,256]
    lfa2_split_kernel<<<lfaBlocks, 256>>>(geom, idx, a1, a2hi, a2lo, w_g2, b_g2, M);
    // 4) out = leaky(x@w_res+b_res) + leaky(a2@w_fin+b_fin)  (un-poisons d_out)
    gemm_fused_final<<<dim3(mTiles, 2), 256, SMEM128>>>(
        x, wres_hi, wres_lo, b_res,
        a2hi, a2lo, wfin_hi, wfin_lo, b_fin, out, M);
}

// round 14
// speedup vs baseline: 1.2935x; 1.0384x over previous
#include <cuda_runtime.h>
#include <cuda_bf16.h>
#include <cstdint>
#include <cstddef>

// Problem constants (ResidualBlock: N=50000, K=16, DIM=256, LeakyReLU slope 0.2)
#define PN    50000
#define PK    16
#define PDIM  256
#define SLOPE 0.2f

typedef __nv_bfloat16 bf16;

// ---------------------------------------------------------------------------
// Scratch (__device__ globals; no allocations allowed)
// ---------------------------------------------------------------------------
__device__ __align__(16) float g_a0[(size_t)PN * 64];     // init MLP out [N,64]
__device__ __align__(16) float g_a1[(size_t)PN * 128];    // LFA1 out     [N,128]
__device__ __align__(16) bf16 g_a2hi[(size_t)PN * 256];
__device__ __align__(16) bf16 g_a2lo[(size_t)PN * 256];
__device__ __align__(16) bf16 g_wres_hi[256 * 256];   // transposed: [n][k]
__device__ __align__(16) bf16 g_wres_lo[256 * 256];
__device__ __align__(16) bf16 g_winit_hi[64 * 256];
__device__ __align__(16) bf16 g_winit_lo[64 * 256];
__device__ __align__(16) bf16 g_wfin_hi[256 * 256];
__device__ __align__(16) bf16 g_wfin_lo[256 * 256];

// ---------------------------------------------------------------------------
// PTX helpers (all plain-sm_103-legal: cp.async, ldmatrix, mma.sync)
// ---------------------------------------------------------------------------
__device__ __forceinline__ uint32_t smem_u32(const void* p) {
    uint32_t a;
    asm("{ .reg .u64 t; cvta.to.shared.u64 t, %1; cvt.u32.u64 %0, t; }"
        : "=r"(a) : "l"(p));
    return a;
}

#define CP16(dst, src) \
    asm volatile("cp.async.cg.shared.global [%0], [%1], 16;" \
                 :: "r"(dst), "l"(src) : "memory")
#define CP_COMMIT() asm volatile("cp.async.commit_group;" ::: "memory")
#define CP_WAIT(n)  asm volatile("cp.async.wait_group %0;" :: "n"(n) : "memory")

#define LDSM_X4(r, addr) \
    asm volatile("ldmatrix.sync.aligned.m8n8.x4.shared.b16 {%0,%1,%2,%3}, [%4];" \
                 : "=r"((r)[0]), "=r"((r)[1]), "=r"((r)[2]), "=r"((r)[3]) \
                 : "r"(addr))

#define MMA16816(d, a, b) \
    asm volatile("mma.sync.aligned.m16n8k16.row.col.f32.bf16.bf16.f32 " \
                 "{%0,%1,%2,%3},{%4,%5,%6,%7},{%8,%9},{%0,%1,%2,%3};" \
                 : "+f"((d)[0]), "+f"((d)[1]), "+f"((d)[2]), "+f"((d)[3]) \
                 : "r"((a)[0]), "r"((a)[1]), "r"((a)[2]), "r"((a)[3]), \
                   "r"((b)[0]), "r"((b)[1]))

// ---------------------------------------------------------------------------
// bf16 hi/lo split helpers
// ---------------------------------------------------------------------------
__device__ __forceinline__ void bf16_split(float v, bf16& h, bf16& l)
{
    h = __float2bfloat16(v);
    l = __float2bfloat16(v - __bfloat162float(h));
}

__device__ __forceinline__ uint2 pack4_bf16(bf16 a, bf16 b, bf16 c, bf16 d)
{
    __nv_bfloat162 p0 = {a, b}, p1 = {c, d};
    uint2 r;
    r.x = *(uint32_t*)&p0;
    r.y = *(uint32_t*)&p1;
    return r;
}

// Convert 8 f32 (two float4) -> 8 hi bf16 (uint4) + 8 lo bf16 (uint4)
__device__ __forceinline__ void split8(const float4 a, const float4 b,
                                       uint4& hv, uint4& lv)
{
    bf16 h[8], l[8];
    bf16_split(a.x, h[0], l[0]); bf16_split(a.y, h[1], l[1]);
    bf16_split(a.z, h[2], l[2]); bf16_split(a.w, h[3], l[3]);
    bf16_split(b.x, h[4], l[4]); bf16_split(b.y, h[5], l[5]);
    bf16_split(b.z, h[6], l[6]); bf16_split(b.w, h[7], l[7]);
    uint2 p0 = pack4_bf16(h[0], h[1], h[2], h[3]);
    uint2 p1 = pack4_bf16(h[4], h[5], h[6], h[7]);
    hv = make_uint4(p0.x, p0.y, p1.x, p1.y);
    p0 = pack4_bf16(l[0], l[1], l[2], l[3]);
    p1 = pack4_bf16(l[4], l[5], l[6], l[7]);
    lv = make_uint4(p0.x, p0.y, p1.x, p1.y);
}

// All three weights: W[K=256, Ncols] f32 -> transposed split bf16 Wt[Ncols][256]
__global__ __launch_bounds__(256) void prep_weights(
    const float* __restrict__ w_res, const float* __restrict__ w_init,
    const float* __restrict__ w_fin,
    bf16* __restrict__ rh, bf16* __restrict__ rl,
    bf16* __restrict__ ih, bf16* __restrict__ il,
    bf16* __restrict__ fh, bf16* __restrict__ fl)
{
    int i = blockIdx.x * blockDim.x + threadIdx.x;
    bf16 h, l;
    if (i < 65536) {                                  // w_res [256,256]
        int n = i >> 8, k = i & 255;
        bf16_split(w_res[(size_t)k * 256 + n], h, l);
        rh[i] = h; rl[i] = l;
    } else if (i < 81920) {                           // w_init [256,64]
        int j = i - 65536;
        int n = j >> 8, k = j & 255;
        bf16_split(w_init[(size_t)k * 64 + n], h, l);
        ih[j] = h; il[j] = l;
    } else if (i < 147456) {                          // w_fin [256,256]
        int j = i - 81920;
        int n = j >> 8, k = j & 255;
        bf16_split(w_fin[(size_t)k * 256 + n], h, l);
        fh[j] = h; fl[j] = l;
    }
}

// ---------------------------------------------------------------------------
// Quad-tile HMMA GEMM, A read as f32 and split in-kernel during staging
// (LDG f32 prefetched one chunk ahead -> CVT -> STS hi/lo; B via cp.async).
// Per 64-wide k-chunk: one residency, three split products (ah*bh+ah*bl+al*bh).
// CTA: BM=64 x BN, 256 threads, warp grid 2(M) x 4(N); 2 CTAs/SM.
// ---------------------------------------------------------------------------
template <int BN>
__global__ __launch_bounds__(256, 2) void gemm_mma_f32a(
    const float* __restrict__ Ax,
    const bf16* __restrict__ Bhi, const bf16* __restrict__ Blo,
    const float* __restrict__ bias, float* __restrict__ C, int M, int Nout)
{
    constexpr int BM = 64, BK = 64, SA = BK + 8;
    constexpr int AT = BM * SA * 2;          // one A split tile (9216 B)
    constexpr int BT = BN * SA * 2;
    constexpr int STAGE = 2 * AT + 2 * BT;   // Ah | Al | Bh | Bl
    constexpr int NT8 = BN / 32;
    constexpr int NPAIR = NT8 / 2;
    constexpr int NCH = 4;

    extern __shared__ __align__(16) char smem[];
    const uint32_t s0 = smem_u32(smem);

    const int tid  = threadIdx.x;
    const int lane = tid & 31;
    const int wid  = tid >> 5;
    const int warpM0 = (wid >> 2) * 32;
    const int warpN0 = (wid & 3) * (BN / 4);
    const int row0 = blockIdx.x * BM;
    const int col0 = blockIdx.y * BN;

    const int lr = tid >> 3;                 // 0..31
    const int lc = (tid & 7) * 8;

    float acc[2][NT8][4];
#pragma unroll
    for (int mt = 0; mt < 2; mt++)
#pragma unroll
        for (int nt = 0; nt < NT8; nt++)
#pragma unroll
            for (int j = 0; j < 4; j++) acc[mt][nt][j] = 0.f;

    auto ldg_A = [&](int kc, float4 (&v)[4]) {
        const int kbase = kc * BK;
#pragma unroll
        for (int i = 0; i < 2; i++) {
            int gr = row0 + lr + 32 * i;
            if (gr > M - 1) gr = M - 1;
            const float* p = Ax + (size_t)gr * 256 + kbase + lc;
            v[2 * i]     = *(const float4*)p;
            v[2 * i + 1] = *(const float4*)(p + 4);
        }
    };
    auto sts_A = [&](const float4 (&v)[4], int slot) {
#pragma unroll
        for (int i = 0; i < 2; i++) {
            const int r = lr + 32 * i;
            uint4 hv, lv;
            split8(v[2 * i], v[2 * i + 1], hv, lv);
            char* dst = smem + slot * STAGE + (r * SA + lc) * 2;
            *(uint4*)dst        = hv;
            *(uint4*)(dst + AT) = lv;
        }
    };
    auto load_B = [&](int kc, int slot) {
        const int kbase = kc * BK;
        const uint32_t base = s0 + slot * STAGE + 2 * AT;
#pragma unroll
        for (int i = 0; i < BN / 32; i++) {
            int r = lr + 32 * i;
            const size_t g = (size_t)(col0 + r) * 256 + kbase + lc;
            CP16(base + (r * SA + lc) * 2,      Bhi + g);
            CP16(base + BT + (r * SA + lc) * 2, Blo + g);
        }
        CP_COMMIT();
    };

    // prologue
    float4 rA[4];
    ldg_A(0, rA);
    sts_A(rA, 0);
    load_B(0, 0);
    ldg_A(1, rA);

    const uint32_t aOff = ((warpM0 + (lane & 15)) * SA + (lane >> 4) * 8) * 2;
    const uint32_t bOff = ((warpN0 + ((lane >> 4) * 8) + (lane & 7)) * SA
                          + ((lane >> 3) & 1) * 8) * 2;

    for (int it = 0; it < NCH; it++) {
        if (it + 1 < NCH) {
            sts_A(rA, (it + 1) & 1);
            load_B(it + 1, (it + 1) & 1);
            if (it + 2 < NCH) ldg_A(it + 2, rA);
            CP_WAIT(1);                      // chunk `it` B resident
        } else {
            CP_WAIT(0);                      // tail: all groups complete
        }
        __syncthreads();

        const uint32_t base = s0 + (it & 1) * STAGE;
        const uint32_t aHi = base + aOff;
        const uint32_t aLo = base + AT + aOff;
        const uint32_t bHi = base + 2 * AT + bOff;
        const uint32_t bLo = base + 2 * AT + BT + bOff;

#pragma unroll
        for (int ks = 0; ks < 4; ks++) {
            uint32_t ah[2][4], al[2][4];
#pragma unroll
            for (int mt = 0; mt < 2; mt++) {
                LDSM_X4(ah[mt], aHi + mt * (16 * SA * 2) + ks * 32);
                LDSM_X4(al[mt], aLo + mt * (16 * SA * 2) + ks * 32);
            }
            uint32_t bh[NT8][2], bl[NT8][2];
#pragma unroll
            for (int np = 0; np < NPAIR; np++) {
                uint32_t t[4];
                LDSM_X4(t, bHi + np * (16 * SA * 2) + ks * 32);
                bh[2 * np][0] = t[0]; bh[2 * np][1] = t[1];
                bh[2 * np + 1][0] = t[2]; bh[2 * np + 1][1] = t[3];
                LDSM_X4(t, bLo + np * (16 * SA * 2) + ks * 32);
                bl[2 * np][0] = t[0]; bl[2 * np][1] = t[1];
                bl[2 * np + 1][0] = t[2]; bl[2 * np + 1][1] = t[3];
            }
#pragma unroll
            for (int mt = 0; mt < 2; mt++)
#pragma unroll
                for (int nt = 0; nt < NT8; nt++) {
                    MMA16816(acc[mt][nt], ah[mt], bh[nt]);
                    MMA16816(acc[mt][nt], ah[mt], bl[nt]);
                    MMA16816(acc[mt][nt], al[mt], bh[nt]);
                }
        }
        __syncthreads();                     // slot safe for reuse
    }

    const int erow = (lane >> 2);
    const int ecol = (lane & 3) * 2;
#pragma unroll
    for (int mt = 0; mt < 2; mt++) {
#pragma unroll
        for (int nt = 0; nt < NT8; nt++) {
            const int col = col0 + warpN0 + nt * 8 + ecol;
            const float2 b2 = *(const float2*)(bias + col);
#pragma unroll
            for (int h = 0; h < 2; h++) {
                const int row = row0 + warpM0 + mt * 16 + erow + h * 8;
                if (row >= M) continue;
                float vx = acc[mt][nt][2 * h]     + b2.x;
                float vy = acc[mt][nt][2 * h + 1] + b2.y;
                vx = vx >= 0.f ? vx : SLOPE * vx;
                vy = vy >= 0.f ? vy : SLOPE * vy;
                *(float2*)(C + (size_t)row * Nout + col) = make_float2(vx, vy);
            }
        }
    }
}

// ---------------------------------------------------------------------------
// Fused final GEMM: out = leaky(x@Wres+b_res) + leaky(a2@Wfin+b_fin)
// Phase 1: A = x f32 (in-kernel split); Phase 2: A = a2 bf16 split (cp.async).
// ---------------------------------------------------------------------------
__global__ __launch_bounds__(256, 2) void gemm_fused_final(
    const float* __restrict__ x,
    const bf16* __restrict__ wrh, const bf16* __restrict__ wrl,
    const float* __restrict__ b_res,
    const bf16* __restrict__ a2hi, const bf16* __restrict__ a2lo,
    const bf16* __restrict__ wfh, const bf16* __restrict__ wfl,
    const float* __restrict__ b_fin,
    float* __restrict__ C, int M)
{
    constexpr int BM = 64, BN = 128, BK = 64, SA = BK + 8;
    constexpr int AT = BM * SA * 2;
    constexpr int BT = BN * SA * 2;
    constexpr int STAGE = 2 * AT + 2 * BT;
    constexpr int NT8 = 4, NPAIR = 2, NCH = 4;

    extern __shared__ __align__(16) char smem[];
    const uint32_t s0 = smem_u32(smem);

    const int tid  = threadIdx.x;
    const int lane = tid & 31;
    const int wid  = tid >> 5;
    const int warpM0 = (wid >> 2) * 32;
    const int warpN0 = (wid & 3) * 32;
    const int row0 = blockIdx.x * BM;
    const int col0 = blockIdx.y * BN;

    const int lr = tid >> 3;
    const int lc = (tid & 7) * 8;

    const uint32_t aOff = ((warpM0 + (lane & 15)) * SA + (lane >> 4) * 8) * 2;
    const uint32_t bOff = ((warpN0 + ((lane >> 4) * 8) + (lane & 7)) * SA
                          + ((lane >> 3) & 1) * 8) * 2;

    float accR[2][NT8][4], accF[2][NT8][4];
#pragma unroll
    for (int mt = 0; mt < 2; mt++)
#pragma unroll
        for (int nt = 0; nt < NT8; nt++)
#pragma unroll
            for (int j = 0; j < 4; j++) { accR[mt][nt][j] = 0.f; accF[mt][nt][j] = 0.f; }

    auto run_phase = [&](float (&acc)[2][NT8][4], const float* Af,
                         const bf16* AH, const bf16* AL,
                         const bf16* BH, const bf16* BL) {
        auto ldg_A = [&](int kc, float4 (&v)[4]) {
            const int kbase = kc * BK;
#pragma unroll
            for (int i = 0; i < 2; i++) {
                int gr = row0 + lr + 32 * i;
                if (gr > M - 1) gr = M - 1;
                const float* p = Af + (size_t)gr * 256 + kbase + lc;
                v[2 * i]     = *(const float4*)p;
                v[2 * i + 1] = *(const float4*)(p + 4);
            }
        };
        auto sts_A = [&](const float4 (&v)[4], int slot) {
#pragma unroll
            for (int i = 0; i < 2; i++) {
                const int r = lr + 32 * i;
                uint4 hv, lv;
                split8(v[2 * i], v[2 * i + 1], hv, lv);
                char* dst = smem + slot * STAGE + (r * SA + lc) * 2;
                *(uint4*)dst        = hv;
                *(uint4*)(dst + AT) = lv;
            }
        };
        auto cp_A = [&](int kc, int slot) {
            const int kbase = kc * BK;
            const uint32_t base = s0 + slot * STAGE;
#pragma unroll
            for (int i = 0; i < 2; i++) {
                int r = lr + 32 * i;
                int gr = row0 + r;
                if (gr > M - 1) gr = M - 1;
                const size_t g = (size_t)gr * 256 + kbase + lc;
                CP16(base + (r * SA + lc) * 2,      AH + g);
                CP16(base + AT + (r * SA + lc) * 2, AL + g);
            }
        };
        auto load_B = [&](int kc, int slot) {
            const int kbase = kc * BK;
            const uint32_t base = s0 + slot * STAGE + 2 * AT;
#pragma unroll
            for (int i = 0; i < 4; i++) {
                int r = lr + 32 * i;
                const size_t g = (size_t)(col0 + r) * 256 + kbase + lc;
                CP16(base + (r * SA + lc) * 2,      BH + g);
                CP16(base + BT + (r * SA + lc) * 2, BL + g);
            }
        };

        const bool f32a = (Af != nullptr);
        float4 rA[4];

        // prologue: stage chunk 0, prefetch chunk 1's A if f32 path
        if (f32a) {
            ldg_A(0, rA);
            sts_A(rA, 0);
            load_B(0, 0);
            CP_COMMIT();
            ldg_A(1, rA);
        } else {
            cp_A(0, 0);
            load_B(0, 0);
            CP_COMMIT();
        }

        for (int it = 0; it < NCH; it++) {
            if (it + 1 < NCH) {
                const int slot = (it + 1) & 1;
                if (f32a) {
                    sts_A(rA, slot);
                    load_B(it + 1, slot);
                    CP_COMMIT();
                    if (it + 2 < NCH) ldg_A(it + 2, rA);
                } else {
                    cp_A(it + 1, slot);
                    load_B(it + 1, slot);
                    CP_COMMIT();
                }
                CP_WAIT(1);
            } else {
                CP_WAIT(0);
            }
            __syncthreads();

            const uint32_t base = s0 + (it & 1) * STAGE;
            const uint32_t aHi = base + aOff;
            const uint32_t aLo = base + AT + aOff;
            const uint32_t bHi = base + 2 * AT + bOff;
            const uint32_t bLo = base + 2 * AT + BT + bOff;

#pragma unroll
            for (int ks = 0; ks < 4; ks++) {
                uint32_t ah[2][4], al[2][4];
#pragma unroll
                for (int mt = 0; mt < 2; mt++) {
                    LDSM_X4(ah[mt], aHi + mt * (16 * SA * 2) + ks * 32);
                    LDSM_X4(al[mt], aLo + mt * (16 * SA * 2) + ks * 32);
                }
                uint32_t bh[NT8][2], bl[NT8][2];
#pragma unroll
                for (int np = 0; np < NPAIR; np++) {
                    uint32_t t[4];
                    LDSM_X4(t, bHi + np * (16 * SA * 2) + ks * 32);
                    bh[2 * np][0] = t[0]; bh[2 * np][1] = t[1];
                    bh[2 * np + 1][0] = t[2]; bh[2 * np + 1][1] = t[3];
                    LDSM_X4(t, bLo + np * (16 * SA * 2) + ks * 32);
                    bl[2 * np][0] = t[0]; bl[2 * np][1] = t[1];
                    bl[2 * np + 1][0] = t[2]; bl[2 * np + 1][1] = t[3];
                }
#pragma unroll
                for (int mt = 0; mt < 2; mt++)
#pragma unroll
                    for (int nt = 0; nt < NT8; nt++) {
                        MMA16816(acc[mt][nt], ah[mt], bh[nt]);
                        MMA16816(acc[mt][nt], ah[mt], bl[nt]);
                        MMA16816(acc[mt][nt], al[mt], bh[nt]);
                    }
            }
            __syncthreads();
        }
    };

    run_phase(accR, x, nullptr, nullptr, wrh, wrl);
    run_phase(accF, nullptr, a2hi, a2lo, wfh, wfl);

    // epilogue: out = leaky(accR + b_res) + leaky(accF + b_fin)
    const int erow = (lane >> 2);
    const int ecol = (lane & 3) * 2;
#pragma unroll
    for (int mt = 0; mt < 2; mt++) {
#pragma unroll
        for (int nt = 0; nt < NT8; nt++) {
            const int col = col0 + warpN0 + nt * 8 + ecol;
            const float2 br = *(const float2*)(b_res + col);
            const float2 bfi = *(const float2*)(b_fin + col);
#pragma unroll
            for (int h = 0; h < 2; h++) {
                const int row = row0 + warpM0 + mt * 16 + erow + h * 8;
                if (row >= M) continue;
                float rx = accR[mt][nt][2 * h]     + br.x;
                float ry = accR[mt][nt][2 * h + 1] + br.y;
                rx = rx >= 0.f ? rx : SLOPE * rx;
                ry = ry >= 0.f ? ry : SLOPE * ry;
                float fx = accF[mt][nt][2 * h]     + bfi.x;
                float fy = accF[mt][nt][2 * h + 1] + bfi.y;
                fx = fx >= 0.f ? fx : SLOPE * fx;
                fy = fy >= 0.f ? fy : SLOPE * fy;
                *(float2*)(C + (size_t)row * 256 + col) =
                    make_float2(rx + fx, ry + fy);
            }
        }
    }
}

// ---------------------------------------------------------------------------
// LFA1 (D=64, f32 out [N,128]): lane owns 2 cols; one LDG.64 per gathered row.
// 256-thread blocks (measured best). UNCHANGED from R13.
// ---------------------------------------------------------------------------
__global__ __launch_bounds__(256) void lfa1_kernel(
    const float* __restrict__ geom, const int* __restrict__ idx,
    const float* __restrict__ feat, float* __restrict__ out,
    const float* __restrict__ wg, const float* __restrict__ bg, int N)
{
    __shared__ float sw[4][64];
    __shared__ float sb[64];
    for (int i = threadIdx.x; i < 4 * 64; i += blockDim.x) sw[i >> 6][i & 63] = wg[i];
    for (int i = threadIdx.x; i < 64; i += blockDim.x) sb[i] = bg[i];
    __syncthreads();

    const int warp = threadIdx.x >> 5;
    const int lane = threadIdx.x & 31;
    const int wpb  = blockDim.x >> 5;
    const int d0   = lane * 2;

    const float2 w0 = *(const float2*)&sw[0][d0];
    const float2 w1 = *(const float2*)&sw[1][d0];
    const float2 w2 = *(const float2*)&sw[2][d0];
    const float2 w3 = *(const float2*)&sw[3][d0];
    const float2 bb = *(const float2*)&sb[d0];
    const float inv = 1.0f / (float)PK;

    for (int n = blockIdx.x * wpb + warp; n < N; n += gridDim.x * wpb) {
        int rows[PK];
        const int4* ip = (const int4*)(idx + (size_t)n * PK);
#pragma unroll
        for (int k4 = 0; k4 < PK / 4; k4++) {
            int4 r = ip[k4];
            rows[4 * k4 + 0] = r.x; rows[4 * k4 + 1] = r.y;
            rows[4 * k4 + 2] = r.z; rows[4 * k4 + 3] = r.w;
        }

        float2 t[PK];
#pragma unroll
        for (int k = 0; k < PK; k++)
            t[k] = *(const float2*)(feat + (size_t)rows[k] * 64 + d0);

        float2 accG = {0.f, 0.f};
        const float4* gp = (const float4*)(geom + (size_t)n * (PK * 4));
#pragma unroll
        for (int k = 0; k < PK; k++) {
            const float4 g = gp[k];
            float vx = bb.x, vy = bb.y;
            vx = fmaf(g.x, w0.x, vx); vy = fmaf(g.x, w0.y, vy);
            vx = fmaf(g.y, w1.x, vx); vy = fmaf(g.y, w1.y, vy);
            vx = fmaf(g.z, w2.x, vx); vy = fmaf(g.z, w2.y, vy);
            vx = fmaf(g.w, w3.x, vx); vy = fmaf(g.w, w3.y, vy);
            vx = vx >= 0.f ? vx : SLOPE * vx;
            vy = vy >= 0.f ? vy : SLOPE * vy;
            accG.x += vx; accG.y += vy;
        }

        float2 accF = {0.f, 0.f};
#pragma unroll
        for (int k = 0; k < PK; k++) { accF.x += t[k].x; accF.y += t[k].y; }

        float* o = out + (size_t)n * 128;
        *(float2*)(o + d0)      = make_float2(accG.x * inv, accG.y * inv);
        *(float2*)(o + 64 + d0) = make_float2(accF.x * inv, accF.y * inv);
    }
}

// ---------------------------------------------------------------------------
// LFA2 (D=128): restructured for occupancy + latency overlap.
// 4 batches of 4 gathers; geom-MLP interleaved inside each batch to hide L2
// latency; per-batch int4 index load (no rows[16] held live).
// __launch_bounds__(256,5): 51-reg cap -> 5 blocks/SM (was 4 @ 54 regs).
// ---------------------------------------------------------------------------
__global__ __launch_bounds__(256, 5) void lfa2_split_kernel(
    const float* __restrict__ geom, const int* __restrict__ idx,
    const float* __restrict__ feat, bf16* __restrict__ ohi,
    bf16* __restrict__ olo,
    const float* __restrict__ wg, const float* __restrict__ bg, int N)
{
    __shared__ float sw[4][128];
    __shared__ float sb[128];
    for (int i = threadIdx.x; i < 4 * 128; i += blockDim.x) sw[i >> 7][i & 127] = wg[i];
    for (int i = threadIdx.x; i < 128; i += blockDim.x) sb[i] = bg[i];
    __syncthreads();

    const int warp = threadIdx.x >> 5;
    const int lane = threadIdx.x & 31;
    const int wpb  = blockDim.x >> 5;
    const int d0   = lane * 4;

    const float4 w0 = *(const float4*)&sw[0][d0];
    const float4 w1 = *(const float4*)&sw[1][d0];
    const float4 w2 = *(const float4*)&sw[2][d0];
    const float4 w3 = *(const float4*)&sw[3][d0];
    const float4 bb = *(const float4*)&sb[d0];
    const float inv = 1.0f / (float)PK;

    for (int n = blockIdx.x * wpb + warp; n < N; n += gridDim.x * wpb) {
        const int4*   ip = (const int4*)(idx + (size_t)n * PK);
        const float4* gp = (const float4*)(geom + (size_t)n * (PK * 4));

        float4 accF = {0.f, 0.f, 0.f, 0.f};
        float4 accG = {0.f, 0.f, 0.f, 0.f};

#pragma unroll
        for (int b = 0; b < 4; b++) {
            // issue 4 gathers (LDG.128) for this batch
            const int4 r = ip[b];
            float4 t0 = *(const float4*)(feat + (size_t)r.x * 128 + d0);
            float4 t1 = *(const float4*)(feat + (size_t)r.y * 128 + d0);
            float4 t2 = *(const float4*)(feat + (size_t)r.z * 128 + d0);
            float4 t3 = *(const float4*)(feat + (size_t)r.w * 128 + d0);

            // independent geom-MLP work (k = 4b .. 4b+3) hides gather latency
#pragma unroll
            for (int kk = 0; kk < 4; kk++) {
                const float4 g = gp[4 * b + kk];
                float vx = bb.x, vy = bb.y, vz = bb.z, vw = bb.w;
                vx = fmaf(g.x, w0.x, vx); vy = fmaf(g.x, w0.y, vy);
                vz = fmaf(g.x, w0.z, vz); vw = fmaf(g.x, w0.w, vw);
                vx = fmaf(g.y, w1.x, vx); vy = fmaf(g.y, w1.y, vy);
                vz = fmaf(g.y, w1.z, vz); vw = fmaf(g.y, w1.w, vw);
                vx = fmaf(g.z, w2.x, vx); vy = fmaf(g.z, w2.y, vy);
                vz = fmaf(g.z, w2.z, vz); vw = fmaf(g.z, w2.w, vw);
                vx = fmaf(g.w, w3.x, vx); vy = fmaf(g.w, w3.y, vy);
                vz = fmaf(g.w, w3.z, vz); vw = fmaf(g.w, w3.w, vw);
                vx = vx >= 0.f ? vx : SLOPE * vx;
                vy = vy >= 0.f ? vy : SLOPE * vy;
                vz = vz >= 0.f ? vz : SLOPE * vz;
                vw = vw >= 0.f ? vw : SLOPE * vw;
                accG.x += vx; accG.y += vy; accG.z += vz; accG.w += vw;
            }

            // consume the gathers
            accF.x += t0.x + t1.x + t2.x + t3.x;
            accF.y += t0.y + t1.y + t2.y + t3.y;
            accF.z += t0.z + t1.z + t2.z + t3.z;
            accF.w += t0.w + t1.w + t2.w + t3.w;
        }

        const size_t base = (size_t)n * 256;
        bf16 h0, h1, h2, h3, l0, l1, l2, l3;
        bf16_split(accG.x * inv, h0, l0); bf16_split(accG.y * inv, h1, l1);
        bf16_split(accG.z * inv, h2, l2); bf16_split(accG.w * inv, h3, l3);
        *(uint2*)(ohi + base + d0) = pack4_bf16(h0, h1, h2, h3);
        *(uint2*)(olo + base + d0) = pack4_bf16(l0, l1, l2, l3);
        bf16_split(accF.x * inv, h0, l0); bf16_split(accF.y * inv, h1, l1);
        bf16_split(accF.z * inv, h2, l2); bf16_split(accF.w * inv, h3, l3);
        *(uint2*)(ohi + base + 128 + d0) = pack4_bf16(h0, h1, h2, h3);
        *(uint2*)(olo + base + 128 + d0) = pack4_bf16(l0, l1, l2, l3);
    }
}

// ---------------------------------------------------------------------------
// Launch
// ---------------------------------------------------------------------------
extern "C" void kernel_launch(void* const* d_in, const int* in_sizes, int n_in,
                              void* d_out, int out_size)
{
    const float* x      = (const float*)d_in[0];
    const float* geom   = (const float*)d_in[1];
    const int*   idx    = (const int*)  d_in[2];
    const float* w_res  = (const float*)d_in[3];
    const float* b_res  = (const float*)d_in[4];
    const float* w_init = (const float*)d_in[5];
    const float* b_init = (const float*)d_in[6];
    const float* w_g1   = (const float*)d_in[7];
    const float* b_g1   = (const float*)d_in[8];
    const float* w_g2   = (const float*)d_in[9];
    const float* b_g2   = (const float*)d_in[10];
    const float* w_fin  = (const float*)d_in[11];
    const float* b_fin  = (const float*)d_in[12];
    float* out = (float*)d_out;

    float *a0, *a1;
    bf16 *a2hi, *a2lo;
    bf16 *wres_hi, *wres_lo, *winit_hi, *winit_lo, *wfin_hi, *wfin_lo;
    cudaGetSymbolAddress((void**)&a0, g_a0);
    cudaGetSymbolAddress((void**)&a1, g_a1);
    cudaGetSymbolAddress((void**)&a2hi, g_a2hi);
    cudaGetSymbolAddress((void**)&a2lo, g_a2lo);
    cudaGetSymbolAddress((void**)&wres_hi, g_wres_hi);
    cudaGetSymbolAddress((void**)&wres_lo, g_wres_lo);
    cudaGetSymbolAddress((void**)&winit_hi, g_winit_hi);
    cudaGetSymbolAddress((void**)&winit_lo, g_winit_lo);
    cudaGetSymbolAddress((void**)&wfin_hi, g_wfin_hi);
    cudaGetSymbolAddress((void**)&wfin_lo, g_wfin_lo);

    // 2-stage quad-tile smem:
    //   BN=128: 2*(2*9216 + 2*18432) = 110592 B ; x2 CTA/SM fits 228KB
    //   BN=64 : 2*(2*9216 + 2*9216)  =  73728 B
    constexpr int SMEM128 = 2 * (2 * 64 * 72 * 2 + 2 * 128 * 72 * 2);
    constexpr int SMEM64  = 2 * (2 * 64 * 72 * 2 + 2 * 64 * 72 * 2);
    cudaFuncSetAttribute(gemm_fused_final, cudaFuncAttributeMaxDynamicSharedMemorySize, SMEM128);
    cudaFuncSetAttribute(gemm_mma_f32a<64>, cudaFuncAttributeMaxDynamicSharedMemorySize, SMEM64);

    const int M = PN;
    const int mTiles = (M + 63) / 64;               // 782
    const int lfaBlocks = (M + 7) / 8;              // 6250 (8 warps/block)

    // prep: weights -> transposed bf16 hi/lo (x is split in-GEMM)
    prep_weights<<<(147456 + 255) / 256, 256>>>(w_res, w_init, w_fin,
                                                wres_hi, wres_lo,
                                                winit_hi, winit_lo,
                                                wfin_hi, wfin_lo);

    // 1) a0 = leaky(x @ w_init + b)   (A = x f32, split in-kernel)
    gemm_mma_f32a<64><<<dim3(mTiles, 1), 256, SMEM64>>>(
        x, winit_hi, winit_lo, b_init, a0, M, 64);
    // 2) LFA1 -> a1 [N,128]
    lfa1_kernel<<<lfaBlocks, 256>>>(geom, idx, a0, a1, w_g1, b_g1, M);
    // 3) LFA2 -> a2 split bf16 [N,256]
    lfa2_split_kernel<<<lfaBlocks, 256>>>(geom, idx, a1, a2hi, a2lo, w_g2, b_g2, M);
    // 4) out = leaky(x@w_res+b_res) + leaky(a2@w_fin+b_fin)  (un-poisons d_out)
    gemm_fused_final<<<dim3(mTiles, 2), 256, SMEM128>>>(
        x, wres_hi, wres_lo, b_res,
        a2hi, a2lo, wfin_hi, wfin_lo, b_fin, out, M);
}